// round 2
// baseline (speedup 1.0000x reference)
#include <cuda_runtime.h>
#include <math.h>

// Problem constants (fixed shapes from reference)
#define T_TOK 8192
#define H_DIM 1024
#define F_DIM 4096
#define E_NUM 8
#define C_CAP 1024   // ceil(T/E)

// ---------------------------------------------------------------------------
// Scratch (no allocations allowed -> __device__ globals)
// ---------------------------------------------------------------------------
__device__ int   g_slot_token[E_NUM * C_CAP];                 // token id per (expert, slot), -1 = empty
__device__ float g_gate[T_TOK];                               // softmax prob of chosen expert
__device__ int   g_expert[T_TOK];                             // argmax expert per token
__device__ float g_hidden[(size_t)E_NUM * C_CAP * F_DIM];     // 134 MB expert hidden activations

// ---------------------------------------------------------------------------
// Kernel 1: gating.  One warp per token: logits = x[t] @ Wg, softmax, argmax.
// ---------------------------------------------------------------------------
__global__ __launch_bounds__(256) void gating_kernel(const float* __restrict__ x,
                                                     const float* __restrict__ Wg) {
    int warp = (blockIdx.x * blockDim.x + threadIdx.x) >> 5;
    int lane = threadIdx.x & 31;
    if (warp >= T_TOK) return;
    const float* xr = x + (size_t)warp * H_DIM;

    float acc[8];
#pragma unroll
    for (int e = 0; e < 8; e++) acc[e] = 0.0f;

    for (int h = lane; h < H_DIM; h += 32) {
        float xv = xr[h];
        const float4* w4 = reinterpret_cast<const float4*>(Wg + (size_t)h * E_NUM);
        float4 a = w4[0];
        float4 b = w4[1];
        acc[0] += xv * a.x; acc[1] += xv * a.y; acc[2] += xv * a.z; acc[3] += xv * a.w;
        acc[4] += xv * b.x; acc[5] += xv * b.y; acc[6] += xv * b.z; acc[7] += xv * b.w;
    }
#pragma unroll
    for (int e = 0; e < 8; e++) {
#pragma unroll
        for (int o = 16; o > 0; o >>= 1)
            acc[e] += __shfl_down_sync(0xffffffffu, acc[e], o);
    }
    if (lane == 0) {
        float m = acc[0];
        int am = 0;
#pragma unroll
        for (int e = 1; e < 8; e++) {
            if (acc[e] > m) { m = acc[e]; am = e; }   // strict > keeps first max (jnp.argmax)
        }
        float s = 0.0f;
#pragma unroll
        for (int e = 0; e < 8; e++) s += expf(acc[e] - m);
        g_expert[warp] = am;
        g_gate[warp]   = 1.0f / s;   // softmax prob at argmax
    }
}

// ---------------------------------------------------------------------------
// Kernel 2: stable per-expert prefix scan + capacity drop.  One block.
// Each thread owns 32 consecutive tokens; per-expert counts are scanned
// across threads so slot ordering matches token order (jnp cumsum).
// ---------------------------------------------------------------------------
__global__ __launch_bounds__(256) void assign_kernel() {
    __shared__ int cnts[256][8];
    const int tid = threadIdx.x;

    // init slot map
    for (int i = tid; i < E_NUM * C_CAP; i += 256) g_slot_token[i] = -1;

    const int per  = T_TOK / 256;      // 32
    const int base = tid * per;

    int loc[8];
#pragma unroll
    for (int e = 0; e < 8; e++) loc[e] = 0;
    for (int j = 0; j < per; j++) loc[g_expert[base + j]]++;
#pragma unroll
    for (int e = 0; e < 8; e++) cnts[tid][e] = loc[e];
    __syncthreads();

    if (tid < 8) {          // serial exclusive scan over 256 thread-chunks per expert
        int run = 0;
        for (int i = 0; i < 256; i++) {
            int v = cnts[i][tid];
            cnts[i][tid] = run;
            run += v;
        }
    }
    __syncthreads();

#pragma unroll
    for (int e = 0; e < 8; e++) loc[e] = cnts[tid][e];
    for (int j = 0; j < per; j++) {
        int t = base + j;
        int e = g_expert[t];
        int s = loc[e]++;
        if (s < C_CAP) g_slot_token[e * C_CAP + s] = t;   // over-capacity tokens dropped
    }
}

// ---------------------------------------------------------------------------
// Kernel 3: FFN1 per expert.  hidden[e,c,f] = relu(x[tok(e,c)] @ W1[e] + b1[e])
// Gathered-A SGEMM: 128x128x16 tile, 256 threads, 8x8 microtile.
// grid = (F/128, C/128, E)
// ---------------------------------------------------------------------------
__global__ __launch_bounds__(256, 2)
void ffn1_kernel(const float* __restrict__ x, const float* __restrict__ W1,
                 const float* __restrict__ b1) {
    const int e  = blockIdx.z;
    const int m0 = blockIdx.y * 128;
    const int n0 = blockIdx.x * 128;

    __shared__ float As[16][128];
    __shared__ float Bs[16][128];
    __shared__ int   rowTok[128];

    const int tid = threadIdx.x;
    if (tid < 128) rowTok[tid] = g_slot_token[e * C_CAP + m0 + tid];
    __syncthreads();

    const float* Bp = W1 + (size_t)e * H_DIM * F_DIM + n0;   // B[h, n] = Bp[h*F + n]

    float acc[8][8];
#pragma unroll
    for (int i = 0; i < 8; i++)
#pragma unroll
        for (int j = 0; j < 8; j++) acc[i][j] = 0.0f;

    const int aRow = tid >> 2;             // 0..63
    const int aK   = (tid & 3) * 4;        // 0,4,8,12
    const int bRow = tid >> 5;             // 0..7
    const int bN   = (tid & 31) * 4;       // 0..124
    const int tm0  = (tid >> 4) * 8;
    const int tn0  = (tid & 15) * 8;

    for (int kt = 0; kt < H_DIM; kt += 16) {
        // ---- load A tile (gathered rows), store transposed As[k][m]
        {
            int  tok0 = rowTok[aRow];
            int  tok1 = rowTok[aRow + 64];
            float4 v0 = make_float4(0.f, 0.f, 0.f, 0.f);
            float4 v1 = make_float4(0.f, 0.f, 0.f, 0.f);
            if (tok0 >= 0) v0 = *reinterpret_cast<const float4*>(x + (size_t)tok0 * H_DIM + kt + aK);
            if (tok1 >= 0) v1 = *reinterpret_cast<const float4*>(x + (size_t)tok1 * H_DIM + kt + aK);
            As[aK + 0][aRow] = v0.x; As[aK + 1][aRow] = v0.y;
            As[aK + 2][aRow] = v0.z; As[aK + 3][aRow] = v0.w;
            As[aK + 0][aRow + 64] = v1.x; As[aK + 1][aRow + 64] = v1.y;
            As[aK + 2][aRow + 64] = v1.z; As[aK + 3][aRow + 64] = v1.w;
        }
        // ---- load B tile
        {
            float4 w0 = *reinterpret_cast<const float4*>(Bp + (size_t)(kt + bRow) * F_DIM + bN);
            float4 w1 = *reinterpret_cast<const float4*>(Bp + (size_t)(kt + bRow + 8) * F_DIM + bN);
            *reinterpret_cast<float4*>(&Bs[bRow][bN])     = w0;
            *reinterpret_cast<float4*>(&Bs[bRow + 8][bN]) = w1;
        }
        __syncthreads();

#pragma unroll
        for (int k = 0; k < 16; k++) {
            float4 a0 = *reinterpret_cast<const float4*>(&As[k][tm0]);
            float4 a1 = *reinterpret_cast<const float4*>(&As[k][tm0 + 4]);
            float4 b0 = *reinterpret_cast<const float4*>(&Bs[k][tn0]);
            float4 b1v = *reinterpret_cast<const float4*>(&Bs[k][tn0 + 4]);
            float av[8] = {a0.x, a0.y, a0.z, a0.w, a1.x, a1.y, a1.z, a1.w};
            float bv[8] = {b0.x, b0.y, b0.z, b0.w, b1v.x, b1v.y, b1v.z, b1v.w};
#pragma unroll
            for (int i = 0; i < 8; i++)
#pragma unroll
                for (int j = 0; j < 8; j++)
                    acc[i][j] += av[i] * bv[j];
        }
        __syncthreads();
    }

    // ---- epilogue: + b1, relu, store to g_hidden
    float* hid = g_hidden + ((size_t)e * C_CAP + m0) * F_DIM + n0;
    const float* b1p = b1 + (size_t)e * F_DIM + n0;
    float bias[8];
#pragma unroll
    for (int j = 0; j < 8; j++) bias[j] = b1p[tn0 + j];
#pragma unroll
    for (int i = 0; i < 8; i++) {
        float4 o0, o1;
        o0.x = fmaxf(acc[i][0] + bias[0], 0.f);
        o0.y = fmaxf(acc[i][1] + bias[1], 0.f);
        o0.z = fmaxf(acc[i][2] + bias[2], 0.f);
        o0.w = fmaxf(acc[i][3] + bias[3], 0.f);
        o1.x = fmaxf(acc[i][4] + bias[4], 0.f);
        o1.y = fmaxf(acc[i][5] + bias[5], 0.f);
        o1.z = fmaxf(acc[i][6] + bias[6], 0.f);
        o1.w = fmaxf(acc[i][7] + bias[7], 0.f);
        float* dst = hid + (size_t)(tm0 + i) * F_DIM + tn0;
        *reinterpret_cast<float4*>(dst)     = o0;
        *reinterpret_cast<float4*>(dst + 4) = o1;
    }
}

// ---------------------------------------------------------------------------
// Kernel 4: FFN2 per expert + gated scatter.
// out[tok(e,c), h] = gate[tok] * (hidden[e,c] @ W2[e] + b2[e])
// grid = (H/128, C/128, E), K = F = 4096
// ---------------------------------------------------------------------------
__global__ __launch_bounds__(256, 2)
void ffn2_kernel(const float* __restrict__ W2, const float* __restrict__ b2,
                 float* __restrict__ out) {
    const int e  = blockIdx.z;
    const int m0 = blockIdx.y * 128;
    const int n0 = blockIdx.x * 128;

    __shared__ float As[16][128];
    __shared__ float Bs[16][128];
    __shared__ int   rowTok[128];
    __shared__ float rowGate[128];

    const int tid = threadIdx.x;
    if (tid < 128) {
        int tk = g_slot_token[e * C_CAP + m0 + tid];
        rowTok[tid]  = tk;
        rowGate[tid] = (tk >= 0) ? g_gate[tk] : 0.0f;
    }
    __syncthreads();

    const float* Ap = g_hidden + ((size_t)e * C_CAP + m0) * F_DIM;   // [128, F]
    const float* Bp = W2 + (size_t)e * F_DIM * H_DIM + n0;           // B[k, n] = Bp[k*H + n]

    float acc[8][8];
#pragma unroll
    for (int i = 0; i < 8; i++)
#pragma unroll
        for (int j = 0; j < 8; j++) acc[i][j] = 0.0f;

    const int aRow = tid >> 2;
    const int aK   = (tid & 3) * 4;
    const int bRow = tid >> 5;
    const int bN   = (tid & 31) * 4;
    const int tm0  = (tid >> 4) * 8;
    const int tn0  = (tid & 15) * 8;

    for (int kt = 0; kt < F_DIM; kt += 16) {
        {
            float4 v0 = *reinterpret_cast<const float4*>(Ap + (size_t)aRow * F_DIM + kt + aK);
            float4 v1 = *reinterpret_cast<const float4*>(Ap + (size_t)(aRow + 64) * F_DIM + kt + aK);
            As[aK + 0][aRow] = v0.x; As[aK + 1][aRow] = v0.y;
            As[aK + 2][aRow] = v0.z; As[aK + 3][aRow] = v0.w;
            As[aK + 0][aRow + 64] = v1.x; As[aK + 1][aRow + 64] = v1.y;
            As[aK + 2][aRow + 64] = v1.z; As[aK + 3][aRow + 64] = v1.w;
        }
        {
            float4 w0 = *reinterpret_cast<const float4*>(Bp + (size_t)(kt + bRow) * H_DIM + bN);
            float4 w1 = *reinterpret_cast<const float4*>(Bp + (size_t)(kt + bRow + 8) * H_DIM + bN);
            *reinterpret_cast<float4*>(&Bs[bRow][bN])     = w0;
            *reinterpret_cast<float4*>(&Bs[bRow + 8][bN]) = w1;
        }
        __syncthreads();

#pragma unroll
        for (int k = 0; k < 16; k++) {
            float4 a0 = *reinterpret_cast<const float4*>(&As[k][tm0]);
            float4 a1 = *reinterpret_cast<const float4*>(&As[k][tm0 + 4]);
            float4 b0 = *reinterpret_cast<const float4*>(&Bs[k][tn0]);
            float4 b1v = *reinterpret_cast<const float4*>(&Bs[k][tn0 + 4]);
            float av[8] = {a0.x, a0.y, a0.z, a0.w, a1.x, a1.y, a1.z, a1.w};
            float bv[8] = {b0.x, b0.y, b0.z, b0.w, b1v.x, b1v.y, b1v.z, b1v.w};
#pragma unroll
            for (int i = 0; i < 8; i++)
#pragma unroll
                for (int j = 0; j < 8; j++)
                    acc[i][j] += av[i] * bv[j];
        }
        __syncthreads();
    }

    // ---- epilogue: + b2, scale by gate, scatter to out rows (kept tokens only)
    const float* b2p = b2 + (size_t)e * H_DIM + n0;
    float bias[8];
#pragma unroll
    for (int j = 0; j < 8; j++) bias[j] = b2p[tn0 + j];
#pragma unroll
    for (int i = 0; i < 8; i++) {
        int tk = rowTok[tm0 + i];
        if (tk < 0) continue;
        float g = rowGate[tm0 + i];
        float4 o0, o1;
        o0.x = g * (acc[i][0] + bias[0]);
        o0.y = g * (acc[i][1] + bias[1]);
        o0.z = g * (acc[i][2] + bias[2]);
        o0.w = g * (acc[i][3] + bias[3]);
        o1.x = g * (acc[i][4] + bias[4]);
        o1.y = g * (acc[i][5] + bias[5]);
        o1.z = g * (acc[i][6] + bias[6]);
        o1.w = g * (acc[i][7] + bias[7]);
        float* dst = out + (size_t)tk * H_DIM + n0 + tn0;
        *reinterpret_cast<float4*>(dst)     = o0;
        *reinterpret_cast<float4*>(dst + 4) = o1;
    }
}

// ---------------------------------------------------------------------------
// Launcher
// ---------------------------------------------------------------------------
extern "C" void kernel_launch(void* const* d_in, const int* in_sizes, int n_in,
                              void* d_out, int out_size) {
    const float* x  = (const float*)d_in[0];   // [4,2048,1024]
    const float* Wg = (const float*)d_in[1];   // [1024,8]
    const float* W1 = (const float*)d_in[2];   // [8,1024,4096]
    const float* b1 = (const float*)d_in[3];   // [8,4096]
    const float* W2 = (const float*)d_in[4];   // [8,4096,1024]
    const float* b2 = (const float*)d_in[5];   // [8,1024]
    float* out = (float*)d_out;                // [4,2048,1024]

    // dropped tokens must output zeros; d_out is poisoned
    cudaMemsetAsync(out, 0, (size_t)out_size * sizeof(float));

    gating_kernel<<<T_TOK / 8, 256>>>(x, Wg);
    assign_kernel<<<1, 256>>>();

    dim3 g1(F_DIM / 128, C_CAP / 128, E_NUM);   // (32, 8, 8)
    ffn1_kernel<<<g1, 256>>>(x, W1, b1);

    dim3 g2(H_DIM / 128, C_CAP / 128, E_NUM);   // (8, 8, 8)
    ffn2_kernel<<<g2, 256>>>(W2, b2, out);
}

// round 4
// speedup vs baseline: 2.0937x; 2.0937x over previous
#include <cuda_runtime.h>
#include <cuda_bf16.h>
#include <math.h>
#include <stdint.h>

// Problem constants
#define T_TOK 8192
#define H_DIM 1024
#define F_DIM 4096
#define E_NUM 8
#define C_CAP 1024

// ---------------------------------------------------------------------------
// Scratch
// ---------------------------------------------------------------------------
__device__ int   g_slot_token[E_NUM * C_CAP];
__device__ float g_gate[T_TOK];
__device__ int   g_expert[T_TOK];
__device__ __nv_bfloat16 g_hidden_hi[(size_t)E_NUM * C_CAP * F_DIM];  // 64 MB
__device__ __nv_bfloat16 g_hidden_lo[(size_t)E_NUM * C_CAP * F_DIM];  // 64 MB

// ---------------------------------------------------------------------------
// Helpers
// ---------------------------------------------------------------------------
__device__ __forceinline__ uint32_t smem_u32(const void* p) {
    uint32_t a;
    asm("{ .reg .u64 t; cvta.to.shared.u64 t, %1; cvt.u32.u64 %0, t; }" : "=r"(a) : "l"(p));
    return a;
}

// pack two floats to bf16x2: low half = a, high half = b (little-endian elem order a,b)
__device__ __forceinline__ uint32_t pack_bf2(float a, float b) {
    uint32_t r;
    asm("cvt.rn.bf16x2.f32 %0, %1, %2;" : "=r"(r) : "f"(b), "f"(a));
    return r;
}
__device__ __forceinline__ void split2(float a, float b, uint32_t& hi, uint32_t& lo) {
    hi = pack_bf2(a, b);
    float ah = __uint_as_float(hi << 16);
    float bh = __uint_as_float(hi & 0xffff0000u);
    lo = pack_bf2(a - ah, b - bh);
}

#define LDSM_X4(r0, r1, r2, r3, addr) \
    asm volatile("ldmatrix.sync.aligned.m8n8.x4.shared.b16 {%0,%1,%2,%3}, [%4];" \
                 : "=r"(r0), "=r"(r1), "=r"(r2), "=r"(r3) : "r"(addr))
#define LDSM_X4_T(r0, r1, r2, r3, addr) \
    asm volatile("ldmatrix.sync.aligned.m8n8.x4.trans.shared.b16 {%0,%1,%2,%3}, [%4];" \
                 : "=r"(r0), "=r"(r1), "=r"(r2), "=r"(r3) : "r"(addr))

__device__ __forceinline__ void mma_bf16(float* d, const uint32_t* a,
                                         uint32_t b0, uint32_t b1) {
    asm volatile(
        "mma.sync.aligned.m16n8k16.row.col.f32.bf16.bf16.f32 "
        "{%0,%1,%2,%3},{%4,%5,%6,%7},{%8,%9},{%0,%1,%2,%3};"
        : "+f"(d[0]), "+f"(d[1]), "+f"(d[2]), "+f"(d[3])
        : "r"(a[0]), "r"(a[1]), "r"(a[2]), "r"(a[3]), "r"(b0), "r"(b1));
}

// SMEM layout per buffer (32 KB): Ah[128][32]bf16 @0, Al @8K, Bh[32][128]bf16 @16K, Bl @24K
#define AH_OFF 0
#define AL_OFF 8192
#define BH_OFF 16384
#define BL_OFF 24576
#define BUF_BYTES 32768
#define DYN_SMEM  (2 * BUF_BYTES + 128)

// swizzled byte offsets (16B chunk granularity)
__device__ __forceinline__ uint32_t aphys(int m, int h) {            // h = k-chunk 0..3 (8 bf16)
    return (uint32_t)(m * 64 + ((h ^ ((m >> 1) & 3)) << 4));
}
__device__ __forceinline__ uint32_t bphys(int k, int c) {            // c = n-chunk 0..15 (8 bf16)
    return (uint32_t)(k * 256 + ((c ^ (k & 7)) << 4));
}

// ---------------------------------------------------------------------------
// Gating: one warp per token
// ---------------------------------------------------------------------------
__global__ __launch_bounds__(256) void gating_kernel(const float* __restrict__ x,
                                                     const float* __restrict__ Wg) {
    int warp = (blockIdx.x * blockDim.x + threadIdx.x) >> 5;
    int lane = threadIdx.x & 31;
    if (warp >= T_TOK) return;
    const float* xr = x + (size_t)warp * H_DIM;
    float acc[8];
#pragma unroll
    for (int e = 0; e < 8; e++) acc[e] = 0.0f;
    for (int h = lane; h < H_DIM; h += 32) {
        float xv = xr[h];
        const float4* w4 = reinterpret_cast<const float4*>(Wg + (size_t)h * E_NUM);
        float4 a = w4[0], b = w4[1];
        acc[0] += xv * a.x; acc[1] += xv * a.y; acc[2] += xv * a.z; acc[3] += xv * a.w;
        acc[4] += xv * b.x; acc[5] += xv * b.y; acc[6] += xv * b.z; acc[7] += xv * b.w;
    }
#pragma unroll
    for (int e = 0; e < 8; e++)
#pragma unroll
        for (int o = 16; o > 0; o >>= 1)
            acc[e] += __shfl_down_sync(0xffffffffu, acc[e], o);
    if (lane == 0) {
        float m = acc[0]; int am = 0;
#pragma unroll
        for (int e = 1; e < 8; e++)
            if (acc[e] > m) { m = acc[e]; am = e; }
        float s = 0.0f;
#pragma unroll
        for (int e = 0; e < 8; e++) s += expf(acc[e] - m);
        g_expert[warp] = am;
        g_gate[warp]   = 1.0f / s;
    }
}

// ---------------------------------------------------------------------------
// Assign: stable per-expert prefix scan + capacity drop
// ---------------------------------------------------------------------------
__global__ __launch_bounds__(256) void assign_kernel() {
    __shared__ int cnts[256][8];
    const int tid = threadIdx.x;
    for (int i = tid; i < E_NUM * C_CAP; i += 256) g_slot_token[i] = -1;
    const int per = T_TOK / 256, base = tid * per;
    int loc[8];
#pragma unroll
    for (int e = 0; e < 8; e++) loc[e] = 0;
    for (int j = 0; j < per; j++) loc[g_expert[base + j]]++;
#pragma unroll
    for (int e = 0; e < 8; e++) cnts[tid][e] = loc[e];
    __syncthreads();
    if (tid < 8) {
        int run = 0;
        for (int i = 0; i < 256; i++) { int v = cnts[i][tid]; cnts[i][tid] = run; run += v; }
    }
    __syncthreads();
#pragma unroll
    for (int e = 0; e < 8; e++) loc[e] = cnts[tid][e];
    for (int j = 0; j < per; j++) {
        int t = base + j, e = g_expert[t], s = loc[e]++;
        if (s < C_CAP) g_slot_token[e * C_CAP + s] = t;
    }
}

// ---------------------------------------------------------------------------
// Shared compute core: one k32 chunk of MMAs from SMEM buffer
// acc[4][4][4]; lane-derived constants passed in.
// ---------------------------------------------------------------------------
__device__ __forceinline__ void compute_chunk(uint32_t bufAbs, float acc[4][4][4],
                                              int lane, int wm, int wn) {
    const uint32_t sA = ((lane & 15) >> 1) & 3;
    const uint32_t hl = lane >> 4;
    const uint32_t aLane = (uint32_t)((wm * 64 + (lane & 15)) * 64);
    const uint32_t bLane = (uint32_t)((lane & 15) * 256);
    const uint32_t sB = lane & 7;

#pragma unroll
    for (int k16 = 0; k16 < 2; ++k16) {
        uint32_t ah[4][4], al[4][4];
        const uint32_t hsw = (((uint32_t)(k16 * 2) + hl) ^ sA) << 4;
#pragma unroll
        for (int i = 0; i < 4; ++i) {
            uint32_t aoff = aLane + (uint32_t)(i * 1024) + hsw;
            LDSM_X4(ah[i][0], ah[i][1], ah[i][2], ah[i][3], bufAbs + AH_OFF + aoff);
            LDSM_X4(al[i][0], al[i][1], al[i][2], al[i][3], bufAbs + AL_OFF + aoff);
        }
#pragma unroll
        for (int j2 = 0; j2 < 2; ++j2) {
            uint32_t csw = (((uint32_t)(wn * 4 + j2 * 2) + hl) ^ sB) << 4;
            uint32_t boff = (uint32_t)(k16 * 16 * 256) + bLane + csw;
            uint32_t bh[4], bl[4];
            LDSM_X4_T(bh[0], bh[1], bh[2], bh[3], bufAbs + BH_OFF + boff);
            LDSM_X4_T(bl[0], bl[1], bl[2], bl[3], bufAbs + BL_OFF + boff);
#pragma unroll
            for (int jj = 0; jj < 2; ++jj) {
                const int j = j2 * 2 + jj;
                const uint32_t bh0 = bh[jj * 2], bh1 = bh[jj * 2 + 1];
                const uint32_t bl0 = bl[jj * 2], bl1 = bl[jj * 2 + 1];
#pragma unroll
                for (int i = 0; i < 4; ++i) {
                    mma_bf16(acc[i][j], ah[i], bh0, bh1);
                    mma_bf16(acc[i][j], ah[i], bl0, bl1);
                    mma_bf16(acc[i][j], al[i], bh0, bh1);
                }
            }
        }
    }
}

// store fp32 quad-pair (8 k-consecutive values as 2 float4) as hi/lo 16B chunks
__device__ __forceinline__ void store_f32x8_split(char* hiDst, char* loDst,
                                                  float4 v0, float4 v1) {
    uint4 hc, lc;
    split2(v0.x, v0.y, hc.x, lc.x);
    split2(v0.z, v0.w, hc.y, lc.y);
    split2(v1.x, v1.y, hc.z, lc.z);
    split2(v1.z, v1.w, hc.w, lc.w);
    *reinterpret_cast<uint4*>(hiDst) = hc;
    *reinterpret_cast<uint4*>(loDst) = lc;
}

// ---------------------------------------------------------------------------
// FFN1: hidden(hi/lo bf16) = relu(gather(x) @ W1[e] + b1[e])
// grid (F/128, C/128, E), 256 threads
// ---------------------------------------------------------------------------
__global__ __launch_bounds__(256)
void ffn1_mma(const float* __restrict__ x, const float* __restrict__ W1,
              const float* __restrict__ b1) {
    extern __shared__ char dynsm[];
    __shared__ int rowTok[128];

    uint32_t sabs0 = smem_u32(dynsm);
    uint32_t pad = (128u - (sabs0 & 127u)) & 127u;
    char* sbase = dynsm + pad;
    uint32_t sabs = sabs0 + pad;

    const int tid = threadIdx.x, lane = tid & 31, wid = tid >> 5;
    const int wm = wid & 1, wn = wid >> 1;
    const int e = blockIdx.z, m0 = blockIdx.y * 128, n0 = blockIdx.x * 128;

    if (tid < 128) rowTok[tid] = g_slot_token[e * C_CAP + m0 + tid];
    __syncthreads();

    float acc[4][4][4];
#pragma unroll
    for (int i = 0; i < 4; i++)
#pragma unroll
        for (int j = 0; j < 4; j++)
#pragma unroll
            for (int r = 0; r < 4; r++) acc[i][j][r] = 0.0f;

    // loader constants
    const int arow = tid >> 1;
    const int akh  = (tid & 1) * 16;              // fp32 k offset in chunk
    const int atok = rowTok[arow];
    const float* aSrc = x + (size_t)(atok < 0 ? 0 : atok) * H_DIM + akh;
    const uint32_t ah0 = aphys(arow, (tid & 1) * 2);
    const uint32_t ah1 = aphys(arow, (tid & 1) * 2 + 1);
    const int bkr = tid >> 3;
    const int bnb = (tid & 7) * 16;
    const uint32_t bo0 = bphys(bkr, (tid & 7) * 2);
    const uint32_t bo1 = bphys(bkr, (tid & 7) * 2 + 1);
    const float* Bg = W1 + (size_t)e * H_DIM * F_DIM + n0;

    float4 pA[4], pB[4];
    // prologue: chunk 0
    {
#pragma unroll
        for (int q = 0; q < 4; q++)
            pA[q] = (atok >= 0) ? *reinterpret_cast<const float4*>(aSrc + q * 4)
                                : make_float4(0.f, 0.f, 0.f, 0.f);
        const float* bs = Bg + (size_t)bkr * F_DIM + bnb;
#pragma unroll
        for (int q = 0; q < 4; q++) pB[q] = *reinterpret_cast<const float4*>(bs + q * 4);
        char* bb = sbase;
        store_f32x8_split(bb + AH_OFF + ah0, bb + AL_OFF + ah0, pA[0], pA[1]);
        store_f32x8_split(bb + AH_OFF + ah1, bb + AL_OFF + ah1, pA[2], pA[3]);
        store_f32x8_split(bb + BH_OFF + bo0, bb + BL_OFF + bo0, pB[0], pB[1]);
        store_f32x8_split(bb + BH_OFF + bo1, bb + BL_OFF + bo1, pB[2], pB[3]);
    }
    __syncthreads();

    const int NCH = H_DIM / 32;   // 32
    for (int c = 0; c < NCH; ++c) {
        const bool hasNext = (c + 1 < NCH);
        if (hasNext) {
            const int kt = (c + 1) * 32;
#pragma unroll
            for (int q = 0; q < 4; q++)
                pA[q] = (atok >= 0) ? *reinterpret_cast<const float4*>(aSrc + kt + q * 4)
                                    : make_float4(0.f, 0.f, 0.f, 0.f);
            const float* bs = Bg + (size_t)(kt + bkr) * F_DIM + bnb;
#pragma unroll
            for (int q = 0; q < 4; q++) pB[q] = *reinterpret_cast<const float4*>(bs + q * 4);
        }
        compute_chunk(sabs + (uint32_t)((c & 1) * BUF_BYTES), acc, lane, wm, wn);
        if (hasNext) {
            char* bb = sbase + ((c + 1) & 1) * BUF_BYTES;
            store_f32x8_split(bb + AH_OFF + ah0, bb + AL_OFF + ah0, pA[0], pA[1]);
            store_f32x8_split(bb + AH_OFF + ah1, bb + AL_OFF + ah1, pA[2], pA[3]);
            store_f32x8_split(bb + BH_OFF + bo0, bb + BL_OFF + bo0, pB[0], pB[1]);
            store_f32x8_split(bb + BH_OFF + bo1, bb + BL_OFF + bo1, pB[2], pB[3]);
            __syncthreads();
        }
    }

    // epilogue: + b1, relu, split bf16 hi/lo
    const int g = lane >> 2, q = (lane & 3) * 2;
    const float* bp = b1 + (size_t)e * F_DIM + n0;
#pragma unroll
    for (int i = 0; i < 4; ++i) {
        const int r0 = m0 + wm * 64 + i * 16 + g;
        const size_t rowBase0 = ((size_t)e * C_CAP + r0) * F_DIM + n0;
        const size_t rowBase1 = rowBase0 + 8 * F_DIM;
#pragma unroll
        for (int j = 0; j < 4; ++j) {
            const int col = wn * 32 + j * 8 + q;
            const float bc0 = bp[col], bc1 = bp[col + 1];
            float v0 = fmaxf(acc[i][j][0] + bc0, 0.f);
            float v1 = fmaxf(acc[i][j][1] + bc1, 0.f);
            float v2 = fmaxf(acc[i][j][2] + bc0, 0.f);
            float v3 = fmaxf(acc[i][j][3] + bc1, 0.f);
            uint32_t hh, ll;
            split2(v0, v1, hh, ll);
            *reinterpret_cast<uint32_t*>(&g_hidden_hi[rowBase0 + col]) = hh;
            *reinterpret_cast<uint32_t*>(&g_hidden_lo[rowBase0 + col]) = ll;
            split2(v2, v3, hh, ll);
            *reinterpret_cast<uint32_t*>(&g_hidden_hi[rowBase1 + col]) = hh;
            *reinterpret_cast<uint32_t*>(&g_hidden_lo[rowBase1 + col]) = ll;
        }
    }
}

// ---------------------------------------------------------------------------
// FFN2: out[tok] = gate * (hidden @ W2[e] + b2[e]);  K = F_DIM
// grid (H/128, C/128, E), 256 threads
// ---------------------------------------------------------------------------
__global__ __launch_bounds__(256)
void ffn2_mma(const float* __restrict__ W2, const float* __restrict__ b2,
              float* __restrict__ out) {
    extern __shared__ char dynsm[];
    __shared__ int   rowTok[128];
    __shared__ float rowGate[128];

    uint32_t sabs0 = smem_u32(dynsm);
    uint32_t pad = (128u - (sabs0 & 127u)) & 127u;
    char* sbase = dynsm + pad;
    uint32_t sabs = sabs0 + pad;

    const int tid = threadIdx.x, lane = tid & 31, wid = tid >> 5;
    const int wm = wid & 1, wn = wid >> 1;
    const int e = blockIdx.z, m0 = blockIdx.y * 128, n0 = blockIdx.x * 128;

    if (tid < 128) {
        int tk = g_slot_token[e * C_CAP + m0 + tid];
        rowTok[tid]  = tk;
        rowGate[tid] = (tk >= 0) ? g_gate[tk] : 0.0f;
    }
    __syncthreads();

    float acc[4][4][4];
#pragma unroll
    for (int i = 0; i < 4; i++)
#pragma unroll
        for (int j = 0; j < 4; j++)
#pragma unroll
            for (int r = 0; r < 4; r++) acc[i][j][r] = 0.0f;

    // loader constants
    const int arow = tid >> 1;
    const int akh  = (tid & 1) * 16;  // bf16 elems
    const size_t hRow = ((size_t)e * C_CAP + m0 + arow) * F_DIM + akh;
    const uint32_t ah0 = aphys(arow, (tid & 1) * 2);
    const uint32_t ah1 = aphys(arow, (tid & 1) * 2 + 1);
    const int bkr = tid >> 3;
    const int bnb = (tid & 7) * 16;
    const uint32_t bo0 = bphys(bkr, (tid & 7) * 2);
    const uint32_t bo1 = bphys(bkr, (tid & 7) * 2 + 1);
    const float* Bg = W2 + (size_t)e * F_DIM * H_DIM + n0;

    uint4 pAh[2], pAl[2];
    float4 pB[4];
    {
        pAh[0] = *reinterpret_cast<const uint4*>(&g_hidden_hi[hRow]);
        pAh[1] = *reinterpret_cast<const uint4*>(&g_hidden_hi[hRow + 8]);
        pAl[0] = *reinterpret_cast<const uint4*>(&g_hidden_lo[hRow]);
        pAl[1] = *reinterpret_cast<const uint4*>(&g_hidden_lo[hRow + 8]);
        const float* bs = Bg + (size_t)bkr * H_DIM + bnb;
#pragma unroll
        for (int q = 0; q < 4; q++) pB[q] = *reinterpret_cast<const float4*>(bs + q * 4);
        char* bb = sbase;
        *reinterpret_cast<uint4*>(bb + AH_OFF + ah0) = pAh[0];
        *reinterpret_cast<uint4*>(bb + AH_OFF + ah1) = pAh[1];
        *reinterpret_cast<uint4*>(bb + AL_OFF + ah0) = pAl[0];
        *reinterpret_cast<uint4*>(bb + AL_OFF + ah1) = pAl[1];
        store_f32x8_split(bb + BH_OFF + bo0, bb + BL_OFF + bo0, pB[0], pB[1]);
        store_f32x8_split(bb + BH_OFF + bo1, bb + BL_OFF + bo1, pB[2], pB[3]);
    }
    __syncthreads();

    const int NCH = F_DIM / 32;   // 128
    for (int c = 0; c < NCH; ++c) {
        const bool hasNext = (c + 1 < NCH);
        if (hasNext) {
            const int kt = (c + 1) * 32;
            pAh[0] = *reinterpret_cast<const uint4*>(&g_hidden_hi[hRow + kt]);
            pAh[1] = *reinterpret_cast<const uint4*>(&g_hidden_hi[hRow + kt + 8]);
            pAl[0] = *reinterpret_cast<const uint4*>(&g_hidden_lo[hRow + kt]);
            pAl[1] = *reinterpret_cast<const uint4*>(&g_hidden_lo[hRow + kt + 8]);
            const float* bs = Bg + (size_t)(kt + bkr) * H_DIM + bnb;
#pragma unroll
            for (int q = 0; q < 4; q++) pB[q] = *reinterpret_cast<const float4*>(bs + q * 4);
        }
        compute_chunk(sabs + (uint32_t)((c & 1) * BUF_BYTES), acc, lane, wm, wn);
        if (hasNext) {
            char* bb = sbase + ((c + 1) & 1) * BUF_BYTES;
            *reinterpret_cast<uint4*>(bb + AH_OFF + ah0) = pAh[0];
            *reinterpret_cast<uint4*>(bb + AH_OFF + ah1) = pAh[1];
            *reinterpret_cast<uint4*>(bb + AL_OFF + ah0) = pAl[0];
            *reinterpret_cast<uint4*>(bb + AL_OFF + ah1) = pAl[1];
            store_f32x8_split(bb + BH_OFF + bo0, bb + BL_OFF + bo0, pB[0], pB[1]);
            store_f32x8_split(bb + BH_OFF + bo1, bb + BL_OFF + bo1, pB[2], pB[3]);
            __syncthreads();
        }
    }

    // epilogue: + b2, gate, scatter fp32 (skip empty slots)
    const int g = lane >> 2, q = (lane & 3) * 2;
    const float* bp = b2 + (size_t)e * H_DIM + n0;
#pragma unroll
    for (int i = 0; i < 4; ++i) {
        const int rl0 = wm * 64 + i * 16 + g;
        const int rl1 = rl0 + 8;
        const int tok0 = rowTok[rl0], tok1 = rowTok[rl1];
        const float g0 = rowGate[rl0], g1 = rowGate[rl1];
#pragma unroll
        for (int j = 0; j < 4; ++j) {
            const int col = wn * 32 + j * 8 + q;
            const float bc0 = bp[col], bc1 = bp[col + 1];
            if (tok0 >= 0) {
                float2 o;
                o.x = g0 * (acc[i][j][0] + bc0);
                o.y = g0 * (acc[i][j][1] + bc1);
                *reinterpret_cast<float2*>(out + (size_t)tok0 * H_DIM + n0 + col) = o;
            }
            if (tok1 >= 0) {
                float2 o;
                o.x = g1 * (acc[i][j][2] + bc0);
                o.y = g1 * (acc[i][j][3] + bc1);
                *reinterpret_cast<float2*>(out + (size_t)tok1 * H_DIM + n0 + col) = o;
            }
        }
    }
}

// ---------------------------------------------------------------------------
// Launcher
// ---------------------------------------------------------------------------
extern "C" void kernel_launch(void* const* d_in, const int* in_sizes, int n_in,
                              void* d_out, int out_size) {
    const float* x  = (const float*)d_in[0];
    const float* Wg = (const float*)d_in[1];
    const float* W1 = (const float*)d_in[2];
    const float* b1 = (const float*)d_in[3];
    const float* W2 = (const float*)d_in[4];
    const float* b2 = (const float*)d_in[5];
    float* out = (float*)d_out;

    cudaFuncSetAttribute(ffn1_mma, cudaFuncAttributeMaxDynamicSharedMemorySize, DYN_SMEM);
    cudaFuncSetAttribute(ffn2_mma, cudaFuncAttributeMaxDynamicSharedMemorySize, DYN_SMEM);

    cudaMemsetAsync(out, 0, (size_t)out_size * sizeof(float));

    gating_kernel<<<T_TOK / 8, 256>>>(x, Wg);
    assign_kernel<<<1, 256>>>();

    dim3 g1(F_DIM / 128, C_CAP / 128, E_NUM);   // (32, 8, 8)
    ffn1_mma<<<g1, 256, DYN_SMEM>>>(x, W1, b1);

    dim3 g2(H_DIM / 128, C_CAP / 128, E_NUM);   // (8, 8, 8)
    ffn2_mma<<<g2, 256, DYN_SMEM>>>(W2, b2, out);
}

// round 5
// speedup vs baseline: 2.1226x; 1.0138x over previous
#include <cuda_runtime.h>
#include <cuda_bf16.h>
#include <math.h>
#include <stdint.h>

// Problem constants
#define T_TOK 8192
#define H_DIM 1024
#define F_DIM 4096
#define E_NUM 8
#define C_CAP 1024

// ---------------------------------------------------------------------------
// Scratch (__device__ globals; allocation is forbidden)
// ---------------------------------------------------------------------------
__device__ int   g_slot_token[E_NUM * C_CAP];
__device__ float g_gate[T_TOK];
__device__ int   g_expert[T_TOK];
__device__ __nv_bfloat16 g_x_hi[(size_t)T_TOK * H_DIM];
__device__ __nv_bfloat16 g_x_lo[(size_t)T_TOK * H_DIM];
__device__ __nv_bfloat16 g_w1_hi[(size_t)E_NUM * H_DIM * F_DIM];
__device__ __nv_bfloat16 g_w1_lo[(size_t)E_NUM * H_DIM * F_DIM];
__device__ __nv_bfloat16 g_w2_hi[(size_t)E_NUM * F_DIM * H_DIM];
__device__ __nv_bfloat16 g_w2_lo[(size_t)E_NUM * F_DIM * H_DIM];
__device__ __nv_bfloat16 g_hidden_hi[(size_t)E_NUM * C_CAP * F_DIM];
__device__ __nv_bfloat16 g_hidden_lo[(size_t)E_NUM * C_CAP * F_DIM];

// ---------------------------------------------------------------------------
// Helpers
// ---------------------------------------------------------------------------
__device__ __forceinline__ uint32_t smem_u32(const void* p) {
    uint32_t a;
    asm("{ .reg .u64 t; cvta.to.shared.u64 t, %1; cvt.u32.u64 %0, t; }" : "=r"(a) : "l"(p));
    return a;
}
__device__ __forceinline__ uint32_t pack_bf2(float a, float b) {
    uint32_t r;
    asm("cvt.rn.bf16x2.f32 %0, %1, %2;" : "=r"(r) : "f"(b), "f"(a));
    return r;
}
__device__ __forceinline__ void split2(float a, float b, uint32_t& hi, uint32_t& lo) {
    hi = pack_bf2(a, b);
    float ah = __uint_as_float(hi << 16);
    float bh = __uint_as_float(hi & 0xffff0000u);
    lo = pack_bf2(a - ah, b - bh);
}

#define LDSM_X4(r0, r1, r2, r3, addr) \
    asm volatile("ldmatrix.sync.aligned.m8n8.x4.shared.b16 {%0,%1,%2,%3}, [%4];" \
                 : "=r"(r0), "=r"(r1), "=r"(r2), "=r"(r3) : "r"(addr))
#define LDSM_X4_T(r0, r1, r2, r3, addr) \
    asm volatile("ldmatrix.sync.aligned.m8n8.x4.trans.shared.b16 {%0,%1,%2,%3}, [%4];" \
                 : "=r"(r0), "=r"(r1), "=r"(r2), "=r"(r3) : "r"(addr))

__device__ __forceinline__ void mma_bf16(float* d, const uint32_t* a,
                                         uint32_t b0, uint32_t b1) {
    asm volatile(
        "mma.sync.aligned.m16n8k16.row.col.f32.bf16.bf16.f32 "
        "{%0,%1,%2,%3},{%4,%5,%6,%7},{%8,%9},{%0,%1,%2,%3};"
        : "+f"(d[0]), "+f"(d[1]), "+f"(d[2]), "+f"(d[3])
        : "r"(a[0]), "r"(a[1]), "r"(a[2]), "r"(a[3]), "r"(b0), "r"(b1));
}

#define CP16(dst, src, sz) \
    asm volatile("cp.async.cg.shared.global [%0], [%1], 16, %2;" \
                 :: "r"(dst), "l"(src), "r"(sz))
#define CP_COMMIT() asm volatile("cp.async.commit_group;")
#define CP_WAIT1()  asm volatile("cp.async.wait_group 1;")

// SMEM: 3 stages x 64KB. Per stage: Ah[128][64]bf16, Al, Bh[64][128]bf16, Bl
#define AH_OFF 0
#define AL_OFF 16384
#define BH_OFF 32768
#define BL_OFF 49152
#define BUF_BYTES 65536
#define STAGES 3
#define DYN_SMEM (STAGES * BUF_BYTES)

// swizzled byte offsets (16B chunk granularity), conflict-free per LDSM phase
__device__ __forceinline__ uint32_t aphys(int row, int h) {   // h: 0..7 (8 bf16 each)
    return (uint32_t)(row * 128 + (((uint32_t)h ^ ((uint32_t)row & 7u)) << 4));
}
__device__ __forceinline__ uint32_t bphys(int k, int c) {     // c: 0..15
    return (uint32_t)(k * 256 + (((uint32_t)c ^ ((uint32_t)k & 7u)) << 4));
}

// ---------------------------------------------------------------------------
// Prep: fp32 -> bf16 hi/lo split (8 elems per thread)
// ---------------------------------------------------------------------------
__global__ __launch_bounds__(256) void split_kernel(const float* __restrict__ src,
                                                    __nv_bfloat16* __restrict__ hi,
                                                    __nv_bfloat16* __restrict__ lo,
                                                    int n8) {
    int i = blockIdx.x * blockDim.x + threadIdx.x;
    if (i >= n8) return;
    const float4* s = reinterpret_cast<const float4*>(src) + (size_t)i * 2;
    float4 v0 = s[0], v1 = s[1];
    uint4 hc, lc;
    split2(v0.x, v0.y, hc.x, lc.x);
    split2(v0.z, v0.w, hc.y, lc.y);
    split2(v1.x, v1.y, hc.z, lc.z);
    split2(v1.z, v1.w, hc.w, lc.w);
    reinterpret_cast<uint4*>(hi)[i] = hc;
    reinterpret_cast<uint4*>(lo)[i] = lc;
}

// ---------------------------------------------------------------------------
// Gating: one warp per token
// ---------------------------------------------------------------------------
__global__ __launch_bounds__(256) void gating_kernel(const float* __restrict__ x,
                                                     const float* __restrict__ Wg) {
    int warp = (blockIdx.x * blockDim.x + threadIdx.x) >> 5;
    int lane = threadIdx.x & 31;
    if (warp >= T_TOK) return;
    const float* xr = x + (size_t)warp * H_DIM;
    float acc[8];
#pragma unroll
    for (int e = 0; e < 8; e++) acc[e] = 0.0f;
    for (int h = lane; h < H_DIM; h += 32) {
        float xv = xr[h];
        const float4* w4 = reinterpret_cast<const float4*>(Wg + (size_t)h * E_NUM);
        float4 a = w4[0], b = w4[1];
        acc[0] += xv * a.x; acc[1] += xv * a.y; acc[2] += xv * a.z; acc[3] += xv * a.w;
        acc[4] += xv * b.x; acc[5] += xv * b.y; acc[6] += xv * b.z; acc[7] += xv * b.w;
    }
#pragma unroll
    for (int e = 0; e < 8; e++)
#pragma unroll
        for (int o = 16; o > 0; o >>= 1)
            acc[e] += __shfl_down_sync(0xffffffffu, acc[e], o);
    if (lane == 0) {
        float m = acc[0]; int am = 0;
#pragma unroll
        for (int e = 1; e < 8; e++)
            if (acc[e] > m) { m = acc[e]; am = e; }
        float s = 0.0f;
#pragma unroll
        for (int e = 0; e < 8; e++) s += expf(acc[e] - m);
        g_expert[warp] = am;
        g_gate[warp]   = 1.0f / s;
    }
}

// ---------------------------------------------------------------------------
// Assign: stable per-expert prefix scan + capacity drop
// ---------------------------------------------------------------------------
__global__ __launch_bounds__(256) void assign_kernel() {
    __shared__ int cnts[256][8];
    const int tid = threadIdx.x;
    for (int i = tid; i < E_NUM * C_CAP; i += 256) g_slot_token[i] = -1;
    const int per = T_TOK / 256, base = tid * per;
    int loc[8];
#pragma unroll
    for (int e = 0; e < 8; e++) loc[e] = 0;
    for (int j = 0; j < per; j++) loc[g_expert[base + j]]++;
#pragma unroll
    for (int e = 0; e < 8; e++) cnts[tid][e] = loc[e];
    __syncthreads();
    if (tid < 8) {
        int run = 0;
        for (int i = 0; i < 256; i++) { int v = cnts[i][tid]; cnts[i][tid] = run; run += v; }
    }
    __syncthreads();
#pragma unroll
    for (int e = 0; e < 8; e++) loc[e] = cnts[tid][e];
    for (int j = 0; j < per; j++) {
        int t = base + j, e = g_expert[t], s = loc[e]++;
        if (s < C_CAP) g_slot_token[e * C_CAP + s] = t;
    }
}

// ---------------------------------------------------------------------------
// Compute one 64-K chunk of 3-term split-bf16 MMAs from a SMEM stage buffer
// ---------------------------------------------------------------------------
__device__ __forceinline__ void compute_chunk64(uint32_t bufAbs, float acc[4][4][4],
                                                int lane, int wm, int wn) {
    const uint32_t sw = (uint32_t)(lane & 7);
    const uint32_t hl = (uint32_t)(lane >> 4);
    const uint32_t aBase = bufAbs + (uint32_t)((wm * 64 + (lane & 15)) * 128);
    const uint32_t bBase = bufAbs + BH_OFF + (uint32_t)((lane & 15) * 256);
#pragma unroll
    for (int k16 = 0; k16 < 4; ++k16) {
        uint32_t ah[4][4], al[4][4];
        const uint32_t hsw = (((uint32_t)(k16 * 2) + hl) ^ sw) << 4;
#pragma unroll
        for (int i = 0; i < 4; ++i) {
            uint32_t aoff = (uint32_t)(i * 2048) + hsw;
            LDSM_X4(ah[i][0], ah[i][1], ah[i][2], ah[i][3], aBase + AH_OFF + aoff);
            LDSM_X4(al[i][0], al[i][1], al[i][2], al[i][3], aBase + AL_OFF + aoff);
        }
#pragma unroll
        for (int j2 = 0; j2 < 2; ++j2) {
            const uint32_t csw = (((uint32_t)(wn * 4 + j2 * 2) + hl) ^ sw) << 4;
            const uint32_t boff = (uint32_t)(k16 * 4096) + csw;
            uint32_t bh[4], bl[4];
            LDSM_X4_T(bh[0], bh[1], bh[2], bh[3], bBase + boff);
            LDSM_X4_T(bl[0], bl[1], bl[2], bl[3], bBase + (BL_OFF - BH_OFF) + boff);
#pragma unroll
            for (int jj = 0; jj < 2; ++jj) {
                const int j = j2 * 2 + jj;
                const uint32_t bh0 = bh[jj * 2], bh1 = bh[jj * 2 + 1];
                const uint32_t bl0 = bl[jj * 2], bl1 = bl[jj * 2 + 1];
#pragma unroll
                for (int i = 0; i < 4; ++i) {
                    mma_bf16(acc[i][j], ah[i], bh0, bh1);
                    mma_bf16(acc[i][j], ah[i], bl0, bl1);
                    mma_bf16(acc[i][j], al[i], bh0, bh1);
                }
            }
        }
    }
}

// ---------------------------------------------------------------------------
// FFN1: hidden(hi/lo bf16) = relu(gather(x) @ W1[e] + b1[e])
// grid (F/128, C/128, E), 256 threads, cp.async 3-stage pipeline
// ---------------------------------------------------------------------------
__global__ __launch_bounds__(256)
void ffn1_mma(const float* __restrict__ b1) {
    extern __shared__ char dynsm[];
    __shared__ int rowTok[128];

    const uint32_t sabs = smem_u32(dynsm);
    const int tid = threadIdx.x, lane = tid & 31, wid = tid >> 5;
    const int wm = wid & 1, wn = wid >> 1;
    const int e = blockIdx.z, m0 = blockIdx.y * 128, n0 = blockIdx.x * 128;

    if (tid < 128) rowTok[tid] = g_slot_token[e * C_CAP + m0 + tid];
    __syncthreads();

    // loader constants
    const int arow = tid >> 1, hb = (tid & 1) * 4;
    const int atok = rowTok[arow];
    const uint32_t asz = (atok >= 0) ? 16u : 0u;
    const __nv_bfloat16* aHsrc = g_x_hi + (size_t)(atok < 0 ? 0 : atok) * H_DIM;
    const __nv_bfloat16* aLsrc = g_x_lo + (size_t)(atok < 0 ? 0 : atok) * H_DIM;
    uint32_t aDst[4];
#pragma unroll
    for (int q = 0; q < 4; q++) aDst[q] = aphys(arow, hb + q);

    const int bk = tid >> 2, cb = (tid & 3) * 4;
    const size_t wBase = (size_t)e * H_DIM * F_DIM + n0;
    uint32_t bDst[4];
#pragma unroll
    for (int q = 0; q < 4; q++) bDst[q] = bphys(bk, cb + q);

    float acc[4][4][4];
#pragma unroll
    for (int i = 0; i < 4; i++)
#pragma unroll
        for (int j = 0; j < 4; j++)
#pragma unroll
            for (int r = 0; r < 4; r++) acc[i][j][r] = 0.0f;

    const int NCH = H_DIM / 64;   // 16

    auto load_stage = [&](int c) {
        const uint32_t bb = sabs + (uint32_t)((c % STAGES) * BUF_BYTES);
        const int kt = c * 64;
#pragma unroll
        for (int q = 0; q < 4; q++) {
            const int koff = kt + (hb + q) * 8;
            CP16(bb + AH_OFF + aDst[q], aHsrc + koff, asz);
            CP16(bb + AL_OFF + aDst[q], aLsrc + koff, asz);
        }
        const size_t wrow = wBase + (size_t)(kt + bk) * F_DIM;
#pragma unroll
        for (int q = 0; q < 4; q++) {
            const int noff = (cb + q) * 8;
            CP16(bb + BH_OFF + bDst[q], g_w1_hi + wrow + noff, 16u);
            CP16(bb + BL_OFF + bDst[q], g_w1_lo + wrow + noff, 16u);
        }
    };

    load_stage(0); CP_COMMIT();
    load_stage(1); CP_COMMIT();

    for (int c = 0; c < NCH; ++c) {
        CP_WAIT1();
        __syncthreads();
        if (c + 2 < NCH) load_stage(c + 2);
        CP_COMMIT();
        compute_chunk64(sabs + (uint32_t)((c % STAGES) * BUF_BYTES), acc, lane, wm, wn);
    }

    // epilogue: + b1, relu, split bf16 hi/lo
    const int g = lane >> 2, q = (lane & 3) * 2;
    const float* bp = b1 + (size_t)e * F_DIM + n0;
#pragma unroll
    for (int i = 0; i < 4; ++i) {
        const int r0 = m0 + wm * 64 + i * 16 + g;
        const size_t rowBase0 = ((size_t)e * C_CAP + r0) * F_DIM + n0;
        const size_t rowBase1 = rowBase0 + 8 * F_DIM;
#pragma unroll
        for (int j = 0; j < 4; ++j) {
            const int col = wn * 32 + j * 8 + q;
            const float bc0 = bp[col], bc1 = bp[col + 1];
            float v0 = fmaxf(acc[i][j][0] + bc0, 0.f);
            float v1 = fmaxf(acc[i][j][1] + bc1, 0.f);
            float v2 = fmaxf(acc[i][j][2] + bc0, 0.f);
            float v3 = fmaxf(acc[i][j][3] + bc1, 0.f);
            uint32_t hh, ll;
            split2(v0, v1, hh, ll);
            *reinterpret_cast<uint32_t*>(&g_hidden_hi[rowBase0 + col]) = hh;
            *reinterpret_cast<uint32_t*>(&g_hidden_lo[rowBase0 + col]) = ll;
            split2(v2, v3, hh, ll);
            *reinterpret_cast<uint32_t*>(&g_hidden_hi[rowBase1 + col]) = hh;
            *reinterpret_cast<uint32_t*>(&g_hidden_lo[rowBase1 + col]) = ll;
        }
    }
}

// ---------------------------------------------------------------------------
// FFN2: out[tok] = gate * (hidden @ W2[e] + b2[e]);  K = F_DIM
// grid (H/128, C/128, E), 256 threads
// ---------------------------------------------------------------------------
__global__ __launch_bounds__(256)
void ffn2_mma(const float* __restrict__ b2, float* __restrict__ out) {
    extern __shared__ char dynsm[];
    __shared__ int   rowTok[128];
    __shared__ float rowGate[128];

    const uint32_t sabs = smem_u32(dynsm);
    const int tid = threadIdx.x, lane = tid & 31, wid = tid >> 5;
    const int wm = wid & 1, wn = wid >> 1;
    const int e = blockIdx.z, m0 = blockIdx.y * 128, n0 = blockIdx.x * 128;

    if (tid < 128) {
        int tk = g_slot_token[e * C_CAP + m0 + tid];
        rowTok[tid]  = tk;
        rowGate[tid] = (tk >= 0) ? g_gate[tk] : 0.0f;
    }
    __syncthreads();

    // loader constants
    const int arow = tid >> 1, hb = (tid & 1) * 4;
    const size_t hRow = ((size_t)e * C_CAP + m0 + arow) * F_DIM;
    uint32_t aDst[4];
#pragma unroll
    for (int q = 0; q < 4; q++) aDst[q] = aphys(arow, hb + q);

    const int bk = tid >> 2, cb = (tid & 3) * 4;
    const size_t wBase = (size_t)e * F_DIM * H_DIM + n0;
    uint32_t bDst[4];
#pragma unroll
    for (int q = 0; q < 4; q++) bDst[q] = bphys(bk, cb + q);

    float acc[4][4][4];
#pragma unroll
    for (int i = 0; i < 4; i++)
#pragma unroll
        for (int j = 0; j < 4; j++)
#pragma unroll
            for (int r = 0; r < 4; r++) acc[i][j][r] = 0.0f;

    const int NCH = F_DIM / 64;   // 64

    auto load_stage = [&](int c) {
        const uint32_t bb = sabs + (uint32_t)((c % STAGES) * BUF_BYTES);
        const int kt = c * 64;
#pragma unroll
        for (int q = 0; q < 4; q++) {
            const int koff = kt + (hb + q) * 8;
            CP16(bb + AH_OFF + aDst[q], g_hidden_hi + hRow + koff, 16u);
            CP16(bb + AL_OFF + aDst[q], g_hidden_lo + hRow + koff, 16u);
        }
        const size_t wrow = wBase + (size_t)(kt + bk) * H_DIM;
#pragma unroll
        for (int q = 0; q < 4; q++) {
            const int noff = (cb + q) * 8;
            CP16(bb + BH_OFF + bDst[q], g_w2_hi + wrow + noff, 16u);
            CP16(bb + BL_OFF + bDst[q], g_w2_lo + wrow + noff, 16u);
        }
    };

    load_stage(0); CP_COMMIT();
    load_stage(1); CP_COMMIT();

    for (int c = 0; c < NCH; ++c) {
        CP_WAIT1();
        __syncthreads();
        if (c + 2 < NCH) load_stage(c + 2);
        CP_COMMIT();
        compute_chunk64(sabs + (uint32_t)((c % STAGES) * BUF_BYTES), acc, lane, wm, wn);
    }

    // epilogue: + b2, gate, scatter fp32 (skip empty slots)
    const int g = lane >> 2, q = (lane & 3) * 2;
    const float* bp = b2 + (size_t)e * H_DIM + n0;
#pragma unroll
    for (int i = 0; i < 4; ++i) {
        const int rl0 = wm * 64 + i * 16 + g;
        const int rl1 = rl0 + 8;
        const int tok0 = rowTok[rl0], tok1 = rowTok[rl1];
        const float g0 = rowGate[rl0], g1 = rowGate[rl1];
#pragma unroll
        for (int j = 0; j < 4; ++j) {
            const int col = wn * 32 + j * 8 + q;
            const float bc0 = bp[col], bc1 = bp[col + 1];
            if (tok0 >= 0) {
                float2 o;
                o.x = g0 * (acc[i][j][0] + bc0);
                o.y = g0 * (acc[i][j][1] + bc1);
                *reinterpret_cast<float2*>(out + (size_t)tok0 * H_DIM + n0 + col) = o;
            }
            if (tok1 >= 0) {
                float2 o;
                o.x = g1 * (acc[i][j][2] + bc0);
                o.y = g1 * (acc[i][j][3] + bc1);
                *reinterpret_cast<float2*>(out + (size_t)tok1 * H_DIM + n0 + col) = o;
            }
        }
    }
}

// ---------------------------------------------------------------------------
// Launcher
// ---------------------------------------------------------------------------
extern "C" void kernel_launch(void* const* d_in, const int* in_sizes, int n_in,
                              void* d_out, int out_size) {
    const float* x  = (const float*)d_in[0];
    const float* Wg = (const float*)d_in[1];
    const float* W1 = (const float*)d_in[2];
    const float* b1 = (const float*)d_in[3];
    const float* W2 = (const float*)d_in[4];
    const float* b2 = (const float*)d_in[5];
    float* out = (float*)d_out;

    cudaFuncSetAttribute(ffn1_mma, cudaFuncAttributeMaxDynamicSharedMemorySize, DYN_SMEM);
    cudaFuncSetAttribute(ffn2_mma, cudaFuncAttributeMaxDynamicSharedMemorySize, DYN_SMEM);

    cudaMemsetAsync(out, 0, (size_t)out_size * sizeof(float));

    // pre-split operands to bf16 hi/lo
    __nv_bfloat16 *xh, *xl, *w1h, *w1l, *w2h, *w2l;
    cudaGetSymbolAddress((void**)&xh,  g_x_hi);
    cudaGetSymbolAddress((void**)&xl,  g_x_lo);
    cudaGetSymbolAddress((void**)&w1h, g_w1_hi);
    cudaGetSymbolAddress((void**)&w1l, g_w1_lo);
    cudaGetSymbolAddress((void**)&w2h, g_w2_hi);
    cudaGetSymbolAddress((void**)&w2l, g_w2_lo);

    const int nx = T_TOK * H_DIM / 8;                 // 1,048,576
    const int nw = E_NUM * H_DIM * F_DIM / 8;         // 4,194,304
    split_kernel<<<(nx + 255) / 256, 256>>>(x,  xh,  xl,  nx);
    split_kernel<<<(nw + 255) / 256, 256>>>(W1, w1h, w1l, nw);
    split_kernel<<<(nw + 255) / 256, 256>>>(W2, w2h, w2l, nw);

    gating_kernel<<<T_TOK / 8, 256>>>(x, Wg);
    assign_kernel<<<1, 256>>>();

    dim3 g1(F_DIM / 128, C_CAP / 128, E_NUM);   // (32, 8, 8)
    ffn1_mma<<<g1, 256, DYN_SMEM>>>(b1);

    dim3 g2(H_DIM / 128, C_CAP / 128, E_NUM);   // (8, 8, 8)
    ffn2_mma<<<g2, 256, DYN_SMEM>>>(b2, out);
}

// round 6
// speedup vs baseline: 2.4185x; 1.1394x over previous
#include <cuda_runtime.h>
#include <cuda_bf16.h>
#include <math.h>
#include <stdint.h>

// Problem constants
#define T_TOK 8192
#define H_DIM 1024
#define F_DIM 4096
#define E_NUM 8
#define C_CAP 1024

// ---------------------------------------------------------------------------
// Scratch
// ---------------------------------------------------------------------------
__device__ int   g_slot_token[E_NUM * C_CAP];
__device__ float g_gate[T_TOK];
__device__ int   g_expert[T_TOK];
__device__ __nv_bfloat16 g_x_hi[(size_t)T_TOK * H_DIM];
__device__ __nv_bfloat16 g_x_lo[(size_t)T_TOK * H_DIM];
__device__ __nv_bfloat16 g_w1_hi[(size_t)E_NUM * H_DIM * F_DIM];
__device__ __nv_bfloat16 g_w1_lo[(size_t)E_NUM * H_DIM * F_DIM];
__device__ __nv_bfloat16 g_w2_hi[(size_t)E_NUM * F_DIM * H_DIM];
__device__ __nv_bfloat16 g_w2_lo[(size_t)E_NUM * F_DIM * H_DIM];
__device__ __nv_bfloat16 g_hidden_hi[(size_t)E_NUM * C_CAP * F_DIM];
__device__ __nv_bfloat16 g_hidden_lo[(size_t)E_NUM * C_CAP * F_DIM];

// ---------------------------------------------------------------------------
// Helpers
// ---------------------------------------------------------------------------
__device__ __forceinline__ uint32_t smem_u32(const void* p) {
    uint32_t a;
    asm("{ .reg .u64 t; cvta.to.shared.u64 t, %1; cvt.u32.u64 %0, t; }" : "=r"(a) : "l"(p));
    return a;
}
__device__ __forceinline__ uint32_t pack_bf2(float a, float b) {
    uint32_t r;
    asm("cvt.rn.bf16x2.f32 %0, %1, %2;" : "=r"(r) : "f"(b), "f"(a));
    return r;
}
__device__ __forceinline__ void split2(float a, float b, uint32_t& hi, uint32_t& lo) {
    hi = pack_bf2(a, b);
    float ah = __uint_as_float(hi << 16);
    float bh = __uint_as_float(hi & 0xffff0000u);
    lo = pack_bf2(a - ah, b - bh);
}

#define LDSM_X4(r0, r1, r2, r3, addr) \
    asm volatile("ldmatrix.sync.aligned.m8n8.x4.shared.b16 {%0,%1,%2,%3}, [%4];" \
                 : "=r"(r0), "=r"(r1), "=r"(r2), "=r"(r3) : "r"(addr))
#define LDSM_X4_T(r0, r1, r2, r3, addr) \
    asm volatile("ldmatrix.sync.aligned.m8n8.x4.trans.shared.b16 {%0,%1,%2,%3}, [%4];" \
                 : "=r"(r0), "=r"(r1), "=r"(r2), "=r"(r3) : "r"(addr))

__device__ __forceinline__ void mma_bf16(float* d, const uint32_t* a,
                                         uint32_t b0, uint32_t b1) {
    asm volatile(
        "mma.sync.aligned.m16n8k16.row.col.f32.bf16.bf16.f32 "
        "{%0,%1,%2,%3},{%4,%5,%6,%7},{%8,%9},{%0,%1,%2,%3};"
        : "+f"(d[0]), "+f"(d[1]), "+f"(d[2]), "+f"(d[3])
        : "r"(a[0]), "r"(a[1]), "r"(a[2]), "r"(a[3]), "r"(b0), "r"(b1));
}

#define CP16(dst, src, sz) \
    asm volatile("cp.async.cg.shared.global [%0], [%1], 16, %2;" \
                 :: "r"(dst), "l"(src), "r"(sz))
#define CP_COMMIT() asm volatile("cp.async.commit_group;")
#define CP_WAIT1()  asm volatile("cp.async.wait_group 1;")

// SMEM stage (36 KB): A rows padded to 80B (conflict-free LDSM: banks 20r mod 32
// all distinct within an 8-row phase). B rows 256B with XOR swizzle.
// Ah[128][80B] @0, Al @10240, Bh[32][256B] @20480, Bl @28672
#define AH_OFF 0
#define AL_OFF 10240
#define BH_OFF 20480
#define BL_OFF 28672
#define BUF_BYTES 36864
#define STAGES 3
#define DYN_SMEM (STAGES * BUF_BYTES)   // 110592 -> 2 CTAs/SM

// ---------------------------------------------------------------------------
// Prep: fp32 -> bf16 hi/lo split
// ---------------------------------------------------------------------------
__global__ __launch_bounds__(256) void split_kernel(const float* __restrict__ src,
                                                    __nv_bfloat16* __restrict__ hi,
                                                    __nv_bfloat16* __restrict__ lo,
                                                    int n8) {
    int i = blockIdx.x * blockDim.x + threadIdx.x;
    if (i >= n8) return;
    const float4* s = reinterpret_cast<const float4*>(src) + (size_t)i * 2;
    float4 v0 = s[0], v1 = s[1];
    uint4 hc, lc;
    split2(v0.x, v0.y, hc.x, lc.x);
    split2(v0.z, v0.w, hc.y, lc.y);
    split2(v1.x, v1.y, hc.z, lc.z);
    split2(v1.z, v1.w, hc.w, lc.w);
    reinterpret_cast<uint4*>(hi)[i] = hc;
    reinterpret_cast<uint4*>(lo)[i] = lc;
}

// ---------------------------------------------------------------------------
// Gating: one warp per token
// ---------------------------------------------------------------------------
__global__ __launch_bounds__(256) void gating_kernel(const float* __restrict__ x,
                                                     const float* __restrict__ Wg) {
    int warp = (blockIdx.x * blockDim.x + threadIdx.x) >> 5;
    int lane = threadIdx.x & 31;
    if (warp >= T_TOK) return;
    const float* xr = x + (size_t)warp * H_DIM;
    float acc[8];
#pragma unroll
    for (int e = 0; e < 8; e++) acc[e] = 0.0f;
    for (int h = lane; h < H_DIM; h += 32) {
        float xv = xr[h];
        const float4* w4 = reinterpret_cast<const float4*>(Wg + (size_t)h * E_NUM);
        float4 a = w4[0], b = w4[1];
        acc[0] += xv * a.x; acc[1] += xv * a.y; acc[2] += xv * a.z; acc[3] += xv * a.w;
        acc[4] += xv * b.x; acc[5] += xv * b.y; acc[6] += xv * b.z; acc[7] += xv * b.w;
    }
#pragma unroll
    for (int e = 0; e < 8; e++)
#pragma unroll
        for (int o = 16; o > 0; o >>= 1)
            acc[e] += __shfl_down_sync(0xffffffffu, acc[e], o);
    if (lane == 0) {
        float m = acc[0]; int am = 0;
#pragma unroll
        for (int e = 1; e < 8; e++)
            if (acc[e] > m) { m = acc[e]; am = e; }
        float s = 0.0f;
#pragma unroll
        for (int e = 0; e < 8; e++) s += expf(acc[e] - m);
        g_expert[warp] = am;
        g_gate[warp]   = 1.0f / s;
    }
}

// ---------------------------------------------------------------------------
// Assign
// ---------------------------------------------------------------------------
__global__ __launch_bounds__(256) void assign_kernel() {
    __shared__ int cnts[256][8];
    const int tid = threadIdx.x;
    for (int i = tid; i < E_NUM * C_CAP; i += 256) g_slot_token[i] = -1;
    const int per = T_TOK / 256, base = tid * per;
    int loc[8];
#pragma unroll
    for (int e = 0; e < 8; e++) loc[e] = 0;
    for (int j = 0; j < per; j++) loc[g_expert[base + j]]++;
#pragma unroll
    for (int e = 0; e < 8; e++) cnts[tid][e] = loc[e];
    __syncthreads();
    if (tid < 8) {
        int run = 0;
        for (int i = 0; i < 256; i++) { int v = cnts[i][tid]; cnts[i][tid] = run; run += v; }
    }
    __syncthreads();
#pragma unroll
    for (int e = 0; e < 8; e++) loc[e] = cnts[tid][e];
    for (int j = 0; j < per; j++) {
        int t = base + j, e = g_expert[t], s = loc[e]++;
        if (s < C_CAP) g_slot_token[e * C_CAP + s] = t;
    }
}

// ---------------------------------------------------------------------------
// Compute one 32-K chunk (2 x k16) of 3-term split-bf16 MMAs
// ---------------------------------------------------------------------------
__device__ __forceinline__ void compute_chunk32(uint32_t bufAbs, float acc[4][4][4],
                                                int lane, int wm, int wn) {
    const uint32_t sw = (uint32_t)(lane & 7);
    const uint32_t hl = (uint32_t)(lane >> 4);
    const uint32_t aBase = bufAbs + (uint32_t)((wm * 64 + (lane & 15)) * 80);
    const uint32_t bBase = bufAbs + BH_OFF + (uint32_t)((lane & 15) * 256);
#pragma unroll
    for (int k16 = 0; k16 < 2; ++k16) {
        // B frags for all 4 j
        uint32_t bh[2][4], bl[2][4];
#pragma unroll
        for (int j2 = 0; j2 < 2; ++j2) {
            const uint32_t csw = (((uint32_t)(wn * 4 + j2 * 2) + hl) ^ sw) << 4;
            const uint32_t boff = (uint32_t)(k16 * 4096) + csw;
            LDSM_X4_T(bh[j2][0], bh[j2][1], bh[j2][2], bh[j2][3], bBase + boff);
            LDSM_X4_T(bl[j2][0], bl[j2][1], bl[j2][2], bl[j2][3],
                      bBase + (BL_OFF - BH_OFF) + boff);
        }
        // A in halves of 2 i's (register pressure)
        const uint32_t hoff = ((uint32_t)(k16 * 2) + hl) << 4;
#pragma unroll
        for (int ih = 0; ih < 2; ++ih) {
            uint32_t ah[2][4], al[2][4];
#pragma unroll
            for (int ii = 0; ii < 2; ++ii) {
                const uint32_t aoff = (uint32_t)((ih * 2 + ii) * 1280) + hoff;
                LDSM_X4(ah[ii][0], ah[ii][1], ah[ii][2], ah[ii][3], aBase + aoff);
                LDSM_X4(al[ii][0], al[ii][1], al[ii][2], al[ii][3],
                        aBase + AL_OFF + aoff);
            }
#pragma unroll
            for (int ii = 0; ii < 2; ++ii) {
                const int i = ih * 2 + ii;
#pragma unroll
                for (int j = 0; j < 4; ++j) {
                    const int j2 = j >> 1, jj = j & 1;
                    const uint32_t b0 = bh[j2][jj * 2], b1 = bh[j2][jj * 2 + 1];
                    const uint32_t c0 = bl[j2][jj * 2], c1 = bl[j2][jj * 2 + 1];
                    mma_bf16(acc[i][j], ah[ii], b0, b1);
                    mma_bf16(acc[i][j], ah[ii], c0, c1);
                    mma_bf16(acc[i][j], al[ii], b0, b1);
                }
            }
        }
    }
}

// ---------------------------------------------------------------------------
// FFN1: hidden(hi/lo bf16) = relu(gather(x) @ W1[e] + b1[e])
// grid (F/128, C/128, E), 256 threads, 2 CTAs/SM
// ---------------------------------------------------------------------------
__global__ __launch_bounds__(256, 2)
void ffn1_mma(const float* __restrict__ b1) {
    extern __shared__ char dynsm[];
    __shared__ int rowTok[128];

    const uint32_t sabs = smem_u32(dynsm);
    const int tid = threadIdx.x, lane = tid & 31, wid = tid >> 5;
    const int wm = wid & 1, wn = wid >> 1;
    const int e = blockIdx.z, m0 = blockIdx.y * 128, n0 = blockIdx.x * 128;

    if (tid < 128) rowTok[tid] = g_slot_token[e * C_CAP + m0 + tid];
    __syncthreads();

    // A loader: row = tid>>1 (0..127), 2 chunks of 16B at c = (tid&1)*2 + q
    const int arow = tid >> 1, ac0 = (tid & 1) * 2;
    const int atok = rowTok[arow];
    const uint32_t asz = (atok >= 0) ? 16u : 0u;
    const __nv_bfloat16* aHsrc = g_x_hi + (size_t)(atok < 0 ? 0 : atok) * H_DIM;
    const __nv_bfloat16* aLsrc = g_x_lo + (size_t)(atok < 0 ? 0 : atok) * H_DIM;
    const uint32_t aD0 = (uint32_t)(arow * 80 + ac0 * 16);

    // B loader: k = tid>>3 (0..31), 2 chunks at c = (tid&7)*2 + q, XOR swizzle
    const int bk = tid >> 3, bc0 = (tid & 7) * 2;
    const size_t wBase = (size_t)e * H_DIM * F_DIM + n0;
    const uint32_t bD0 = (uint32_t)(bk * 256 + (((uint32_t)bc0 ^ ((uint32_t)bk & 7u)) << 4));
    const uint32_t bD1 = (uint32_t)(bk * 256 + ((((uint32_t)bc0 + 1u) ^ ((uint32_t)bk & 7u)) << 4));

    float acc[4][4][4];
#pragma unroll
    for (int i = 0; i < 4; i++)
#pragma unroll
        for (int j = 0; j < 4; j++)
#pragma unroll
            for (int r = 0; r < 4; r++) acc[i][j][r] = 0.0f;

    const int NCH = H_DIM / 32;   // 32

    auto load_stage = [&](int c) {
        const uint32_t bb = sabs + (uint32_t)((c % STAGES) * BUF_BYTES);
        const int kt = c * 32;
        CP16(bb + AH_OFF + aD0,      aHsrc + kt + ac0 * 8,       asz);
        CP16(bb + AH_OFF + aD0 + 16, aHsrc + kt + ac0 * 8 + 8,   asz);
        CP16(bb + AL_OFF + aD0,      aLsrc + kt + ac0 * 8,       asz);
        CP16(bb + AL_OFF + aD0 + 16, aLsrc + kt + ac0 * 8 + 8,   asz);
        const size_t wrow = wBase + (size_t)(kt + bk) * F_DIM;
        CP16(bb + BH_OFF + bD0, g_w1_hi + wrow + bc0 * 8,     16u);
        CP16(bb + BH_OFF + bD1, g_w1_hi + wrow + bc0 * 8 + 8, 16u);
        CP16(bb + BL_OFF + bD0, g_w1_lo + wrow + bc0 * 8,     16u);
        CP16(bb + BL_OFF + bD1, g_w1_lo + wrow + bc0 * 8 + 8, 16u);
    };

    load_stage(0); CP_COMMIT();
    load_stage(1); CP_COMMIT();

    for (int c = 0; c < NCH; ++c) {
        CP_WAIT1();
        __syncthreads();
        if (c + 2 < NCH) load_stage(c + 2);
        CP_COMMIT();
        compute_chunk32(sabs + (uint32_t)((c % STAGES) * BUF_BYTES), acc, lane, wm, wn);
    }

    // epilogue: + b1, relu, split bf16 hi/lo
    const int g = lane >> 2, q = (lane & 3) * 2;
    const float* bp = b1 + (size_t)e * F_DIM + n0;
#pragma unroll
    for (int i = 0; i < 4; ++i) {
        const int r0 = m0 + wm * 64 + i * 16 + g;
        const size_t rowBase0 = ((size_t)e * C_CAP + r0) * F_DIM + n0;
        const size_t rowBase1 = rowBase0 + 8 * F_DIM;
#pragma unroll
        for (int j = 0; j < 4; ++j) {
            const int col = wn * 32 + j * 8 + q;
            const float bc0 = bp[col], bc1 = bp[col + 1];
            float v0 = fmaxf(acc[i][j][0] + bc0, 0.f);
            float v1 = fmaxf(acc[i][j][1] + bc1, 0.f);
            float v2 = fmaxf(acc[i][j][2] + bc0, 0.f);
            float v3 = fmaxf(acc[i][j][3] + bc1, 0.f);
            uint32_t hh, ll;
            split2(v0, v1, hh, ll);
            *reinterpret_cast<uint32_t*>(&g_hidden_hi[rowBase0 + col]) = hh;
            *reinterpret_cast<uint32_t*>(&g_hidden_lo[rowBase0 + col]) = ll;
            split2(v2, v3, hh, ll);
            *reinterpret_cast<uint32_t*>(&g_hidden_hi[rowBase1 + col]) = hh;
            *reinterpret_cast<uint32_t*>(&g_hidden_lo[rowBase1 + col]) = ll;
        }
    }
}

// ---------------------------------------------------------------------------
// FFN2: out[tok] = gate * (hidden @ W2[e] + b2[e])
// grid (H/128, C/128, E), 256 threads, 2 CTAs/SM
// ---------------------------------------------------------------------------
__global__ __launch_bounds__(256, 2)
void ffn2_mma(const float* __restrict__ b2, float* __restrict__ out) {
    extern __shared__ char dynsm[];
    __shared__ int   rowTok[128];
    __shared__ float rowGate[128];

    const uint32_t sabs = smem_u32(dynsm);
    const int tid = threadIdx.x, lane = tid & 31, wid = tid >> 5;
    const int wm = wid & 1, wn = wid >> 1;
    const int e = blockIdx.z, m0 = blockIdx.y * 128, n0 = blockIdx.x * 128;

    if (tid < 128) {
        int tk = g_slot_token[e * C_CAP + m0 + tid];
        rowTok[tid]  = tk;
        rowGate[tid] = (tk >= 0) ? g_gate[tk] : 0.0f;
    }
    __syncthreads();

    const int arow = tid >> 1, ac0 = (tid & 1) * 2;
    const size_t hRow = ((size_t)e * C_CAP + m0 + arow) * F_DIM;
    const uint32_t aD0 = (uint32_t)(arow * 80 + ac0 * 16);

    const int bk = tid >> 3, bc0 = (tid & 7) * 2;
    const size_t wBase = (size_t)e * F_DIM * H_DIM + n0;
    const uint32_t bD0 = (uint32_t)(bk * 256 + (((uint32_t)bc0 ^ ((uint32_t)bk & 7u)) << 4));
    const uint32_t bD1 = (uint32_t)(bk * 256 + ((((uint32_t)bc0 + 1u) ^ ((uint32_t)bk & 7u)) << 4));

    float acc[4][4][4];
#pragma unroll
    for (int i = 0; i < 4; i++)
#pragma unroll
        for (int j = 0; j < 4; j++)
#pragma unroll
            for (int r = 0; r < 4; r++) acc[i][j][r] = 0.0f;

    const int NCH = F_DIM / 32;   // 128

    auto load_stage = [&](int c) {
        const uint32_t bb = sabs + (uint32_t)((c % STAGES) * BUF_BYTES);
        const int kt = c * 32;
        CP16(bb + AH_OFF + aD0,      g_hidden_hi + hRow + kt + ac0 * 8,     16u);
        CP16(bb + AH_OFF + aD0 + 16, g_hidden_hi + hRow + kt + ac0 * 8 + 8, 16u);
        CP16(bb + AL_OFF + aD0,      g_hidden_lo + hRow + kt + ac0 * 8,     16u);
        CP16(bb + AL_OFF + aD0 + 16, g_hidden_lo + hRow + kt + ac0 * 8 + 8, 16u);
        const size_t wrow = wBase + (size_t)(kt + bk) * H_DIM;
        CP16(bb + BH_OFF + bD0, g_w2_hi + wrow + bc0 * 8,     16u);
        CP16(bb + BH_OFF + bD1, g_w2_hi + wrow + bc0 * 8 + 8, 16u);
        CP16(bb + BL_OFF + bD0, g_w2_lo + wrow + bc0 * 8,     16u);
        CP16(bb + BL_OFF + bD1, g_w2_lo + wrow + bc0 * 8 + 8, 16u);
    };

    load_stage(0); CP_COMMIT();
    load_stage(1); CP_COMMIT();

    for (int c = 0; c < NCH; ++c) {
        CP_WAIT1();
        __syncthreads();
        if (c + 2 < NCH) load_stage(c + 2);
        CP_COMMIT();
        compute_chunk32(sabs + (uint32_t)((c % STAGES) * BUF_BYTES), acc, lane, wm, wn);
    }

    // epilogue: + b2, gate, scatter fp32
    const int g = lane >> 2, q = (lane & 3) * 2;
    const float* bp = b2 + (size_t)e * H_DIM + n0;
#pragma unroll
    for (int i = 0; i < 4; ++i) {
        const int rl0 = wm * 64 + i * 16 + g;
        const int rl1 = rl0 + 8;
        const int tok0 = rowTok[rl0], tok1 = rowTok[rl1];
        const float g0 = rowGate[rl0], g1 = rowGate[rl1];
#pragma unroll
        for (int j = 0; j < 4; ++j) {
            const int col = wn * 32 + j * 8 + q;
            const float bc0 = bp[col], bc1 = bp[col + 1];
            if (tok0 >= 0) {
                float2 o;
                o.x = g0 * (acc[i][j][0] + bc0);
                o.y = g0 * (acc[i][j][1] + bc1);
                *reinterpret_cast<float2*>(out + (size_t)tok0 * H_DIM + n0 + col) = o;
            }
            if (tok1 >= 0) {
                float2 o;
                o.x = g1 * (acc[i][j][2] + bc0);
                o.y = g1 * (acc[i][j][3] + bc1);
                *reinterpret_cast<float2*>(out + (size_t)tok1 * H_DIM + n0 + col) = o;
            }
        }
    }
}

// ---------------------------------------------------------------------------
// Launcher
// ---------------------------------------------------------------------------
extern "C" void kernel_launch(void* const* d_in, const int* in_sizes, int n_in,
                              void* d_out, int out_size) {
    const float* x  = (const float*)d_in[0];
    const float* Wg = (const float*)d_in[1];
    const float* W1 = (const float*)d_in[2];
    const float* b1 = (const float*)d_in[3];
    const float* W2 = (const float*)d_in[4];
    const float* b2 = (const float*)d_in[5];
    float* out = (float*)d_out;

    cudaFuncSetAttribute(ffn1_mma, cudaFuncAttributeMaxDynamicSharedMemorySize, DYN_SMEM);
    cudaFuncSetAttribute(ffn2_mma, cudaFuncAttributeMaxDynamicSharedMemorySize, DYN_SMEM);

    cudaMemsetAsync(out, 0, (size_t)out_size * sizeof(float));

    __nv_bfloat16 *xh, *xl, *w1h, *w1l, *w2h, *w2l;
    cudaGetSymbolAddress((void**)&xh,  g_x_hi);
    cudaGetSymbolAddress((void**)&xl,  g_x_lo);
    cudaGetSymbolAddress((void**)&w1h, g_w1_hi);
    cudaGetSymbolAddress((void**)&w1l, g_w1_lo);
    cudaGetSymbolAddress((void**)&w2h, g_w2_hi);
    cudaGetSymbolAddress((void**)&w2l, g_w2_lo);

    const int nx = T_TOK * H_DIM / 8;
    const int nw = E_NUM * H_DIM * F_DIM / 8;
    split_kernel<<<(nx + 255) / 256, 256>>>(x,  xh,  xl,  nx);
    split_kernel<<<(nw + 255) / 256, 256>>>(W1, w1h, w1l, nw);
    split_kernel<<<(nw + 255) / 256, 256>>>(W2, w2h, w2l, nw);

    gating_kernel<<<T_TOK / 8, 256>>>(x, Wg);
    assign_kernel<<<1, 256>>>();

    dim3 g1(F_DIM / 128, C_CAP / 128, E_NUM);   // (32, 8, 8)
    ffn1_mma<<<g1, 256, DYN_SMEM>>>(b1);

    dim3 g2(H_DIM / 128, C_CAP / 128, E_NUM);   // (8, 8, 8)
    ffn2_mma<<<g2, 256, DYN_SMEM>>>(b2, out);
}

// round 7
// speedup vs baseline: 2.7601x; 1.1413x over previous
#include <cuda_runtime.h>
#include <cuda_fp16.h>
#include <math.h>
#include <stdint.h>

// Problem constants
#define T_TOK 8192
#define H_DIM 1024
#define F_DIM 4096
#define E_NUM 8
#define C_CAP 1024

// ---------------------------------------------------------------------------
// Scratch
// ---------------------------------------------------------------------------
__device__ int    g_slot_token[E_NUM * C_CAP];
__device__ float  g_gate[T_TOK];
__device__ int    g_expert[T_TOK];
__device__ __half g_x_hi[(size_t)T_TOK * H_DIM];
__device__ __half g_x_lo[(size_t)T_TOK * H_DIM];
__device__ __half g_w1[(size_t)E_NUM * H_DIM * F_DIM];
__device__ __half g_w2[(size_t)E_NUM * F_DIM * H_DIM];
__device__ __half g_hidden_hi[(size_t)E_NUM * C_CAP * F_DIM];
__device__ __half g_hidden_lo[(size_t)E_NUM * C_CAP * F_DIM];

// ---------------------------------------------------------------------------
// Helpers
// ---------------------------------------------------------------------------
__device__ __forceinline__ uint32_t smem_u32(const void* p) {
    uint32_t a;
    asm("{ .reg .u64 t; cvta.to.shared.u64 t, %1; cvt.u32.u64 %0, t; }" : "=r"(a) : "l"(p));
    return a;
}
__device__ __forceinline__ uint32_t h2_u32(__half2 h) {
    return *reinterpret_cast<uint32_t*>(&h);
}
// fp32 pair -> fp16 hi/lo split (packed half2 words)
__device__ __forceinline__ void split2h(float a, float b, uint32_t& hi, uint32_t& lo) {
    __half2 h = __floats2half2_rn(a, b);
    float2 hf = __half22float2(h);
    __half2 l = __floats2half2_rn(a - hf.x, b - hf.y);
    hi = h2_u32(h);
    lo = h2_u32(l);
}

#define LDSM_X4(r0, r1, r2, r3, addr) \
    asm volatile("ldmatrix.sync.aligned.m8n8.x4.shared.b16 {%0,%1,%2,%3}, [%4];" \
                 : "=r"(r0), "=r"(r1), "=r"(r2), "=r"(r3) : "r"(addr))
#define LDSM_X4_T(r0, r1, r2, r3, addr) \
    asm volatile("ldmatrix.sync.aligned.m8n8.x4.trans.shared.b16 {%0,%1,%2,%3}, [%4];" \
                 : "=r"(r0), "=r"(r1), "=r"(r2), "=r"(r3) : "r"(addr))

__device__ __forceinline__ void mma_fp16(float* d, const uint32_t* a,
                                         uint32_t b0, uint32_t b1) {
    asm volatile(
        "mma.sync.aligned.m16n8k16.row.col.f32.f16.f16.f32 "
        "{%0,%1,%2,%3},{%4,%5,%6,%7},{%8,%9},{%0,%1,%2,%3};"
        : "+f"(d[0]), "+f"(d[1]), "+f"(d[2]), "+f"(d[3])
        : "r"(a[0]), "r"(a[1]), "r"(a[2]), "r"(a[3]), "r"(b0), "r"(b1));
}

#define CP16(dst, src, sz) \
    asm volatile("cp.async.cg.shared.global [%0], [%1], 16, %2;" \
                 :: "r"(dst), "l"(src), "r"(sz))
#define CP_COMMIT() asm volatile("cp.async.commit_group;")
#define CP_WAIT1()  asm volatile("cp.async.wait_group 1;")

// SMEM stage (28 KB): Ahi[128][80B] @0, Alo @10240, B[32][256B] @20480.
// A rows padded to 80B -> LDSM 8-row phases hit 32 distinct banks. B XOR-swizzled.
#define AH_OFF 0
#define AL_OFF 10240
#define BH_OFF 20480
#define BUF_BYTES 28672
#define STAGES 3
#define DYN_SMEM (STAGES * BUF_BYTES)   // 86016 -> 2 CTAs/SM

// ---------------------------------------------------------------------------
// Prep kernels
// ---------------------------------------------------------------------------
__global__ __launch_bounds__(256) void splitx_kernel(const float* __restrict__ src,
                                                     __half* __restrict__ hi,
                                                     __half* __restrict__ lo,
                                                     int n8) {
    int i = blockIdx.x * blockDim.x + threadIdx.x;
    if (i >= n8) return;
    const float4* s = reinterpret_cast<const float4*>(src) + (size_t)i * 2;
    float4 v0 = s[0], v1 = s[1];
    uint4 hc, lc;
    split2h(v0.x, v0.y, hc.x, lc.x);
    split2h(v0.z, v0.w, hc.y, lc.y);
    split2h(v1.x, v1.y, hc.z, lc.z);
    split2h(v1.z, v1.w, hc.w, lc.w);
    reinterpret_cast<uint4*>(hi)[i] = hc;
    reinterpret_cast<uint4*>(lo)[i] = lc;
}

__global__ __launch_bounds__(256) void convh_kernel(const float* __restrict__ src,
                                                    __half* __restrict__ dst,
                                                    int n8) {
    int i = blockIdx.x * blockDim.x + threadIdx.x;
    if (i >= n8) return;
    const float4* s = reinterpret_cast<const float4*>(src) + (size_t)i * 2;
    float4 v0 = s[0], v1 = s[1];
    uint4 o;
    o.x = h2_u32(__floats2half2_rn(v0.x, v0.y));
    o.y = h2_u32(__floats2half2_rn(v0.z, v0.w));
    o.z = h2_u32(__floats2half2_rn(v1.x, v1.y));
    o.w = h2_u32(__floats2half2_rn(v1.z, v1.w));
    reinterpret_cast<uint4*>(dst)[i] = o;
}

// ---------------------------------------------------------------------------
// Gating: one warp per token
// ---------------------------------------------------------------------------
__global__ __launch_bounds__(256) void gating_kernel(const float* __restrict__ x,
                                                     const float* __restrict__ Wg) {
    int warp = (blockIdx.x * blockDim.x + threadIdx.x) >> 5;
    int lane = threadIdx.x & 31;
    if (warp >= T_TOK) return;
    const float* xr = x + (size_t)warp * H_DIM;
    float acc[8];
#pragma unroll
    for (int e = 0; e < 8; e++) acc[e] = 0.0f;
    for (int h = lane; h < H_DIM; h += 32) {
        float xv = xr[h];
        const float4* w4 = reinterpret_cast<const float4*>(Wg + (size_t)h * E_NUM);
        float4 a = w4[0], b = w4[1];
        acc[0] += xv * a.x; acc[1] += xv * a.y; acc[2] += xv * a.z; acc[3] += xv * a.w;
        acc[4] += xv * b.x; acc[5] += xv * b.y; acc[6] += xv * b.z; acc[7] += xv * b.w;
    }
#pragma unroll
    for (int e = 0; e < 8; e++)
#pragma unroll
        for (int o = 16; o > 0; o >>= 1)
            acc[e] += __shfl_down_sync(0xffffffffu, acc[e], o);
    if (lane == 0) {
        float m = acc[0]; int am = 0;
#pragma unroll
        for (int e = 1; e < 8; e++)
            if (acc[e] > m) { m = acc[e]; am = e; }
        float s = 0.0f;
#pragma unroll
        for (int e = 0; e < 8; e++) s += expf(acc[e] - m);
        g_expert[warp] = am;
        g_gate[warp]   = 1.0f / s;
    }
}

// ---------------------------------------------------------------------------
// Assign: stable per-expert prefix scan + capacity drop
// ---------------------------------------------------------------------------
__global__ __launch_bounds__(256) void assign_kernel() {
    __shared__ int cnts[256][8];
    const int tid = threadIdx.x;
    for (int i = tid; i < E_NUM * C_CAP; i += 256) g_slot_token[i] = -1;
    const int per = T_TOK / 256, base = tid * per;
    int loc[8];
#pragma unroll
    for (int e = 0; e < 8; e++) loc[e] = 0;
    for (int j = 0; j < per; j++) loc[g_expert[base + j]]++;
#pragma unroll
    for (int e = 0; e < 8; e++) cnts[tid][e] = loc[e];
    __syncthreads();
    if (tid < 8) {
        int run = 0;
        for (int i = 0; i < 256; i++) { int v = cnts[i][tid]; cnts[i][tid] = run; run += v; }
    }
    __syncthreads();
#pragma unroll
    for (int e = 0; e < 8; e++) loc[e] = cnts[tid][e];
    for (int j = 0; j < per; j++) {
        int t = base + j, e = g_expert[t], s = loc[e]++;
        if (s < C_CAP) g_slot_token[e * C_CAP + s] = t;
    }
}

// ---------------------------------------------------------------------------
// Compute one 32-K chunk: 2-term fp16 split (Ah*B + Al*B), fp32 accumulate
// ---------------------------------------------------------------------------
__device__ __forceinline__ void compute_chunk32(uint32_t bufAbs, float acc[4][4][4],
                                                int lane, int wm, int wn) {
    const uint32_t sw = (uint32_t)(lane & 7);
    const uint32_t hl = (uint32_t)(lane >> 4);
    const uint32_t aBase = bufAbs + (uint32_t)((wm * 64 + (lane & 15)) * 80);
    const uint32_t bBase = bufAbs + BH_OFF + (uint32_t)((lane & 15) * 256);
#pragma unroll
    for (int k16 = 0; k16 < 2; ++k16) {
        // B frags for all 4 j (single fp16 weights)
        uint32_t bh[2][4];
#pragma unroll
        for (int j2 = 0; j2 < 2; ++j2) {
            const uint32_t csw = (((uint32_t)(wn * 4 + j2 * 2) + hl) ^ sw) << 4;
            LDSM_X4_T(bh[j2][0], bh[j2][1], bh[j2][2], bh[j2][3],
                      bBase + (uint32_t)(k16 * 4096) + csw);
        }
        const uint32_t hoff = ((uint32_t)(k16 * 2) + hl) << 4;
#pragma unroll
        for (int ih = 0; ih < 2; ++ih) {
            uint32_t ah[2][4], al[2][4];
#pragma unroll
            for (int ii = 0; ii < 2; ++ii) {
                const uint32_t aoff = (uint32_t)((ih * 2 + ii) * 1280) + hoff;
                LDSM_X4(ah[ii][0], ah[ii][1], ah[ii][2], ah[ii][3], aBase + aoff);
                LDSM_X4(al[ii][0], al[ii][1], al[ii][2], al[ii][3],
                        aBase + AL_OFF + aoff);
            }
#pragma unroll
            for (int ii = 0; ii < 2; ++ii) {
                const int i = ih * 2 + ii;
#pragma unroll
                for (int j = 0; j < 4; ++j) {
                    const uint32_t b0 = bh[j >> 1][(j & 1) * 2];
                    const uint32_t b1 = bh[j >> 1][(j & 1) * 2 + 1];
                    mma_fp16(acc[i][j], ah[ii], b0, b1);
                    mma_fp16(acc[i][j], al[ii], b0, b1);
                }
            }
        }
    }
}

// ---------------------------------------------------------------------------
// FFN1: hidden(hi/lo fp16) = relu(gather(x) @ W1[e] + b1[e])
// grid (F/128, C/128, E), 256 threads, 2 CTAs/SM
// ---------------------------------------------------------------------------
__global__ __launch_bounds__(256, 2)
void ffn1_mma(const float* __restrict__ b1) {
    extern __shared__ char dynsm[];
    __shared__ int rowTok[128];

    const uint32_t sabs = smem_u32(dynsm);
    const int tid = threadIdx.x, lane = tid & 31, wid = tid >> 5;
    const int wm = wid & 1, wn = wid >> 1;
    const int e = blockIdx.z, m0 = blockIdx.y * 128, n0 = blockIdx.x * 128;

    if (tid < 128) rowTok[tid] = g_slot_token[e * C_CAP + m0 + tid];
    __syncthreads();

    // A loader: thread owns one full row of one part (hi/lo): 4 chunks of 16B
    const int part = tid >> 7;          // 0 = hi, 1 = lo
    const int arow = tid & 127;
    const int atok = rowTok[arow];
    const uint32_t asz = (atok >= 0) ? 16u : 0u;
    const __half* aSrc = (part ? g_x_lo : g_x_hi) + (size_t)(atok < 0 ? 0 : atok) * H_DIM;
    const uint32_t aDst = (uint32_t)(part ? AL_OFF : AH_OFF) + (uint32_t)(arow * 80);

    // B loader: k = tid>>3 (0..31), 2 chunks at c = (tid&7)*2 + q, XOR swizzle
    const int bk = tid >> 3, bc0 = (tid & 7) * 2;
    const size_t wBase = (size_t)e * H_DIM * F_DIM + n0;
    const uint32_t bD0 = BH_OFF + (uint32_t)(bk * 256) + ((((uint32_t)bc0)     ^ ((uint32_t)bk & 7u)) << 4);
    const uint32_t bD1 = BH_OFF + (uint32_t)(bk * 256) + ((((uint32_t)bc0 + 1u) ^ ((uint32_t)bk & 7u)) << 4);

    float acc[4][4][4];
#pragma unroll
    for (int i = 0; i < 4; i++)
#pragma unroll
        for (int j = 0; j < 4; j++)
#pragma unroll
            for (int r = 0; r < 4; r++) acc[i][j][r] = 0.0f;

    const int NCH = H_DIM / 32;   // 32

    auto load_stage = [&](int c) {
        const uint32_t bb = sabs + (uint32_t)((c % STAGES) * BUF_BYTES);
        const int kt = c * 32;
#pragma unroll
        for (int q = 0; q < 4; q++)
            CP16(bb + aDst + q * 16, aSrc + kt + q * 8, asz);
        const size_t wrow = wBase + (size_t)(kt + bk) * F_DIM;
        CP16(bb + bD0, g_w1 + wrow + bc0 * 8,     16u);
        CP16(bb + bD1, g_w1 + wrow + bc0 * 8 + 8, 16u);
    };

    load_stage(0); CP_COMMIT();
    load_stage(1); CP_COMMIT();

    for (int c = 0; c < NCH; ++c) {
        CP_WAIT1();
        __syncthreads();
        if (c + 2 < NCH) load_stage(c + 2);
        CP_COMMIT();
        compute_chunk32(sabs + (uint32_t)((c % STAGES) * BUF_BYTES), acc, lane, wm, wn);
    }

    // epilogue: + b1, relu, split fp16 hi/lo
    const int g = lane >> 2, q = (lane & 3) * 2;
    const float* bp = b1 + (size_t)e * F_DIM + n0;
#pragma unroll
    for (int i = 0; i < 4; ++i) {
        const int r0 = m0 + wm * 64 + i * 16 + g;
        const size_t rowBase0 = ((size_t)e * C_CAP + r0) * F_DIM + n0;
        const size_t rowBase1 = rowBase0 + 8 * F_DIM;
#pragma unroll
        for (int j = 0; j < 4; ++j) {
            const int col = wn * 32 + j * 8 + q;
            const float bc0 = bp[col], bc1 = bp[col + 1];
            float v0 = fmaxf(acc[i][j][0] + bc0, 0.f);
            float v1 = fmaxf(acc[i][j][1] + bc1, 0.f);
            float v2 = fmaxf(acc[i][j][2] + bc0, 0.f);
            float v3 = fmaxf(acc[i][j][3] + bc1, 0.f);
            uint32_t hh, ll;
            split2h(v0, v1, hh, ll);
            *reinterpret_cast<uint32_t*>(&g_hidden_hi[rowBase0 + col]) = hh;
            *reinterpret_cast<uint32_t*>(&g_hidden_lo[rowBase0 + col]) = ll;
            split2h(v2, v3, hh, ll);
            *reinterpret_cast<uint32_t*>(&g_hidden_hi[rowBase1 + col]) = hh;
            *reinterpret_cast<uint32_t*>(&g_hidden_lo[rowBase1 + col]) = ll;
        }
    }
}

// ---------------------------------------------------------------------------
// FFN2: out[tok] = gate * (hidden @ W2[e] + b2[e]);  K = F_DIM
// grid (H/128, C/128, E), 256 threads, 2 CTAs/SM
// ---------------------------------------------------------------------------
__global__ __launch_bounds__(256, 2)
void ffn2_mma(const float* __restrict__ b2, float* __restrict__ out) {
    extern __shared__ char dynsm[];
    __shared__ int   rowTok[128];
    __shared__ float rowGate[128];

    const uint32_t sabs = smem_u32(dynsm);
    const int tid = threadIdx.x, lane = tid & 31, wid = tid >> 5;
    const int wm = wid & 1, wn = wid >> 1;
    const int e = blockIdx.z, m0 = blockIdx.y * 128, n0 = blockIdx.x * 128;

    if (tid < 128) {
        int tk = g_slot_token[e * C_CAP + m0 + tid];
        rowTok[tid]  = tk;
        rowGate[tid] = (tk >= 0) ? g_gate[tk] : 0.0f;
    }
    __syncthreads();

    const int part = tid >> 7;
    const int arow = tid & 127;
    const size_t hRow = ((size_t)e * C_CAP + m0 + arow) * F_DIM;
    const __half* aSrc = (part ? g_hidden_lo : g_hidden_hi) + hRow;
    const uint32_t aDst = (uint32_t)(part ? AL_OFF : AH_OFF) + (uint32_t)(arow * 80);

    const int bk = tid >> 3, bc0 = (tid & 7) * 2;
    const size_t wBase = (size_t)e * F_DIM * H_DIM + n0;
    const uint32_t bD0 = BH_OFF + (uint32_t)(bk * 256) + ((((uint32_t)bc0)     ^ ((uint32_t)bk & 7u)) << 4);
    const uint32_t bD1 = BH_OFF + (uint32_t)(bk * 256) + ((((uint32_t)bc0 + 1u) ^ ((uint32_t)bk & 7u)) << 4);

    float acc[4][4][4];
#pragma unroll
    for (int i = 0; i < 4; i++)
#pragma unroll
        for (int j = 0; j < 4; j++)
#pragma unroll
            for (int r = 0; r < 4; r++) acc[i][j][r] = 0.0f;

    const int NCH = F_DIM / 32;   // 128

    auto load_stage = [&](int c) {
        const uint32_t bb = sabs + (uint32_t)((c % STAGES) * BUF_BYTES);
        const int kt = c * 32;
#pragma unroll
        for (int q = 0; q < 4; q++)
            CP16(bb + aDst + q * 16, aSrc + kt + q * 8, 16u);
        const size_t wrow = wBase + (size_t)(kt + bk) * H_DIM;
        CP16(bb + bD0, g_w2 + wrow + bc0 * 8,     16u);
        CP16(bb + bD1, g_w2 + wrow + bc0 * 8 + 8, 16u);
    };

    load_stage(0); CP_COMMIT();
    load_stage(1); CP_COMMIT();

    for (int c = 0; c < NCH; ++c) {
        CP_WAIT1();
        __syncthreads();
        if (c + 2 < NCH) load_stage(c + 2);
        CP_COMMIT();
        compute_chunk32(sabs + (uint32_t)((c % STAGES) * BUF_BYTES), acc, lane, wm, wn);
    }

    // epilogue: + b2, gate, scatter fp32
    const int g = lane >> 2, q = (lane & 3) * 2;
    const float* bp = b2 + (size_t)e * H_DIM + n0;
#pragma unroll
    for (int i = 0; i < 4; ++i) {
        const int rl0 = wm * 64 + i * 16 + g;
        const int rl1 = rl0 + 8;
        const int tok0 = rowTok[rl0], tok1 = rowTok[rl1];
        const float g0 = rowGate[rl0], g1 = rowGate[rl1];
#pragma unroll
        for (int j = 0; j < 4; ++j) {
            const int col = wn * 32 + j * 8 + q;
            const float bc0 = bp[col], bc1 = bp[col + 1];
            if (tok0 >= 0) {
                float2 o;
                o.x = g0 * (acc[i][j][0] + bc0);
                o.y = g0 * (acc[i][j][1] + bc1);
                *reinterpret_cast<float2*>(out + (size_t)tok0 * H_DIM + n0 + col) = o;
            }
            if (tok1 >= 0) {
                float2 o;
                o.x = g1 * (acc[i][j][2] + bc0);
                o.y = g1 * (acc[i][j][3] + bc1);
                *reinterpret_cast<float2*>(out + (size_t)tok1 * H_DIM + n0 + col) = o;
            }
        }
    }
}

// ---------------------------------------------------------------------------
// Launcher
// ---------------------------------------------------------------------------
extern "C" void kernel_launch(void* const* d_in, const int* in_sizes, int n_in,
                              void* d_out, int out_size) {
    const float* x  = (const float*)d_in[0];
    const float* Wg = (const float*)d_in[1];
    const float* W1 = (const float*)d_in[2];
    const float* b1 = (const float*)d_in[3];
    const float* W2 = (const float*)d_in[4];
    const float* b2 = (const float*)d_in[5];
    float* out = (float*)d_out;

    cudaFuncSetAttribute(ffn1_mma, cudaFuncAttributeMaxDynamicSharedMemorySize, DYN_SMEM);
    cudaFuncSetAttribute(ffn2_mma, cudaFuncAttributeMaxDynamicSharedMemorySize, DYN_SMEM);

    cudaMemsetAsync(out, 0, (size_t)out_size * sizeof(float));

    __half *xh, *xl, *w1p, *w2p;
    cudaGetSymbolAddress((void**)&xh,  g_x_hi);
    cudaGetSymbolAddress((void**)&xl,  g_x_lo);
    cudaGetSymbolAddress((void**)&w1p, g_w1);
    cudaGetSymbolAddress((void**)&w2p, g_w2);

    const int nx = T_TOK * H_DIM / 8;
    const int nw = E_NUM * H_DIM * F_DIM / 8;
    splitx_kernel<<<(nx + 255) / 256, 256>>>(x,  xh, xl, nx);
    convh_kernel<<<(nw + 255) / 256, 256>>>(W1, w1p, nw);
    convh_kernel<<<(nw + 255) / 256, 256>>>(W2, w2p, nw);

    gating_kernel<<<T_TOK / 8, 256>>>(x, Wg);
    assign_kernel<<<1, 256>>>();

    dim3 g1(F_DIM / 128, C_CAP / 128, E_NUM);   // (32, 8, 8)
    ffn1_mma<<<g1, 256, DYN_SMEM>>>(b1);

    dim3 g2(H_DIM / 128, C_CAP / 128, E_NUM);   // (8, 8, 8)
    ffn2_mma<<<g2, 256, DYN_SMEM>>>(b2, out);
}

// round 8
// speedup vs baseline: 5.5356x; 2.0056x over previous
#include <cuda_runtime.h>
#include <cuda_fp16.h>
#include <math.h>
#include <stdint.h>

// Problem constants
#define T_TOK 8192
#define H_DIM 1024
#define F_DIM 4096
#define E_NUM 8
#define C_CAP 1024

// ---------------------------------------------------------------------------
// Scratch
// ---------------------------------------------------------------------------
__device__ int    g_slot_token[E_NUM * C_CAP];
__device__ float  g_gate[T_TOK];
__device__ int    g_expert[T_TOK];
__device__ __half g_x16[(size_t)T_TOK * H_DIM];
__device__ __half g_w1[(size_t)E_NUM * H_DIM * F_DIM];
__device__ __half g_w2[(size_t)E_NUM * F_DIM * H_DIM];
__device__ __half g_hidden[(size_t)E_NUM * C_CAP * F_DIM];

// ---------------------------------------------------------------------------
// Helpers
// ---------------------------------------------------------------------------
__device__ __forceinline__ uint32_t smem_u32(const void* p) {
    uint32_t a;
    asm("{ .reg .u64 t; cvta.to.shared.u64 t, %1; cvt.u32.u64 %0, t; }" : "=r"(a) : "l"(p));
    return a;
}
__device__ __forceinline__ uint32_t h2_u32(__half2 h) {
    return *reinterpret_cast<uint32_t*>(&h);
}

#define LDSM_X4(r0, r1, r2, r3, addr) \
    asm volatile("ldmatrix.sync.aligned.m8n8.x4.shared.b16 {%0,%1,%2,%3}, [%4];" \
                 : "=r"(r0), "=r"(r1), "=r"(r2), "=r"(r3) : "r"(addr))
#define LDSM_X4_T(r0, r1, r2, r3, addr) \
    asm volatile("ldmatrix.sync.aligned.m8n8.x4.trans.shared.b16 {%0,%1,%2,%3}, [%4];" \
                 : "=r"(r0), "=r"(r1), "=r"(r2), "=r"(r3) : "r"(addr))

__device__ __forceinline__ void mma_fp16(float* d, const uint32_t* a,
                                         uint32_t b0, uint32_t b1) {
    asm volatile(
        "mma.sync.aligned.m16n8k16.row.col.f32.f16.f16.f32 "
        "{%0,%1,%2,%3},{%4,%5,%6,%7},{%8,%9},{%0,%1,%2,%3};"
        : "+f"(d[0]), "+f"(d[1]), "+f"(d[2]), "+f"(d[3])
        : "r"(a[0]), "r"(a[1]), "r"(a[2]), "r"(a[3]), "r"(b0), "r"(b1));
}

#define CP16(dst, src, sz) \
    asm volatile("cp.async.cg.shared.global [%0], [%1], 16, %2;" \
                 :: "r"(dst), "l"(src), "r"(sz))
#define CP_COMMIT() asm volatile("cp.async.commit_group;")
#define CP_WAIT1()  asm volatile("cp.async.wait_group 1;")

// SMEM stage (18 KB): A[128][80B] @0 (rows padded to 80B: LDSM phases
// conflict-free), B[32][256B] @10240 (XOR swizzle).
#define A_OFF 0
#define B_OFF 10240
#define BUF_BYTES 18432
#define STAGES 3
#define DYN_SMEM (STAGES * BUF_BYTES)   // 55296

// ---------------------------------------------------------------------------
// Prep: fp32 -> fp16 convert (8 elems/thread)
// ---------------------------------------------------------------------------
__global__ __launch_bounds__(256) void convh_kernel(const float* __restrict__ src,
                                                    __half* __restrict__ dst,
                                                    int n8) {
    int i = blockIdx.x * blockDim.x + threadIdx.x;
    if (i >= n8) return;
    const float4* s = reinterpret_cast<const float4*>(src) + (size_t)i * 2;
    float4 v0 = s[0], v1 = s[1];
    uint4 o;
    o.x = h2_u32(__floats2half2_rn(v0.x, v0.y));
    o.y = h2_u32(__floats2half2_rn(v0.z, v0.w));
    o.z = h2_u32(__floats2half2_rn(v1.x, v1.y));
    o.w = h2_u32(__floats2half2_rn(v1.z, v1.w));
    reinterpret_cast<uint4*>(dst)[i] = o;
}

// ---------------------------------------------------------------------------
// Gating: one warp per token
// ---------------------------------------------------------------------------
__global__ __launch_bounds__(256) void gating_kernel(const float* __restrict__ x,
                                                     const float* __restrict__ Wg) {
    int warp = (blockIdx.x * blockDim.x + threadIdx.x) >> 5;
    int lane = threadIdx.x & 31;
    if (warp >= T_TOK) return;
    const float* xr = x + (size_t)warp * H_DIM;
    float acc[8];
#pragma unroll
    for (int e = 0; e < 8; e++) acc[e] = 0.0f;
    for (int h = lane; h < H_DIM; h += 32) {
        float xv = xr[h];
        const float4* w4 = reinterpret_cast<const float4*>(Wg + (size_t)h * E_NUM);
        float4 a = w4[0], b = w4[1];
        acc[0] += xv * a.x; acc[1] += xv * a.y; acc[2] += xv * a.z; acc[3] += xv * a.w;
        acc[4] += xv * b.x; acc[5] += xv * b.y; acc[6] += xv * b.z; acc[7] += xv * b.w;
    }
#pragma unroll
    for (int e = 0; e < 8; e++)
#pragma unroll
        for (int o = 16; o > 0; o >>= 1)
            acc[e] += __shfl_down_sync(0xffffffffu, acc[e], o);
    if (lane == 0) {
        float m = acc[0]; int am = 0;
#pragma unroll
        for (int e = 1; e < 8; e++)
            if (acc[e] > m) { m = acc[e]; am = e; }
        float s = 0.0f;
#pragma unroll
        for (int e = 0; e < 8; e++) s += expf(acc[e] - m);
        g_expert[warp] = am;
        g_gate[warp]   = 1.0f / s;
    }
}

// ---------------------------------------------------------------------------
// Assign: stable per-expert prefix scan + capacity drop
// ---------------------------------------------------------------------------
__global__ __launch_bounds__(256) void assign_kernel() {
    __shared__ int cnts[256][8];
    const int tid = threadIdx.x;
    for (int i = tid; i < E_NUM * C_CAP; i += 256) g_slot_token[i] = -1;
    const int per = T_TOK / 256, base = tid * per;
    int loc[8];
#pragma unroll
    for (int e = 0; e < 8; e++) loc[e] = 0;
    for (int j = 0; j < per; j++) loc[g_expert[base + j]]++;
#pragma unroll
    for (int e = 0; e < 8; e++) cnts[tid][e] = loc[e];
    __syncthreads();
    if (tid < 8) {
        int run = 0;
        for (int i = 0; i < 256; i++) { int v = cnts[i][tid]; cnts[i][tid] = run; run += v; }
    }
    __syncthreads();
#pragma unroll
    for (int e = 0; e < 8; e++) loc[e] = cnts[tid][e];
    for (int j = 0; j < per; j++) {
        int t = base + j, e = g_expert[t], s = loc[e]++;
        if (s < C_CAP) g_slot_token[e * C_CAP + s] = t;
    }
}

// ---------------------------------------------------------------------------
// Compute one 32-K chunk: plain fp16 MMA, fp32 accumulate
// ---------------------------------------------------------------------------
__device__ __forceinline__ void compute_chunk32(uint32_t bufAbs, float acc[4][4][4],
                                                int lane, int wm, int wn) {
    const uint32_t sw = (uint32_t)(lane & 7);
    const uint32_t hl = (uint32_t)(lane >> 4);
    const uint32_t aBase = bufAbs + (uint32_t)((wm * 64 + (lane & 15)) * 80);
    const uint32_t bBase = bufAbs + B_OFF + (uint32_t)((lane & 15) * 256);
#pragma unroll
    for (int k16 = 0; k16 < 2; ++k16) {
        uint32_t bh[2][4];
#pragma unroll
        for (int j2 = 0; j2 < 2; ++j2) {
            const uint32_t csw = (((uint32_t)(wn * 4 + j2 * 2) + hl) ^ sw) << 4;
            LDSM_X4_T(bh[j2][0], bh[j2][1], bh[j2][2], bh[j2][3],
                      bBase + (uint32_t)(k16 * 4096) + csw);
        }
        const uint32_t hoff = ((uint32_t)(k16 * 2) + hl) << 4;
        uint32_t ah[4][4];
#pragma unroll
        for (int i = 0; i < 4; ++i) {
            const uint32_t aoff = (uint32_t)(i * 1280) + hoff;
            LDSM_X4(ah[i][0], ah[i][1], ah[i][2], ah[i][3], aBase + aoff);
        }
#pragma unroll
        for (int i = 0; i < 4; ++i)
#pragma unroll
            for (int j = 0; j < 4; ++j) {
                const uint32_t b0 = bh[j >> 1][(j & 1) * 2];
                const uint32_t b1 = bh[j >> 1][(j & 1) * 2 + 1];
                mma_fp16(acc[i][j], ah[i], b0, b1);
            }
    }
}

// ---------------------------------------------------------------------------
// FFN1: hidden(fp16) = relu(gather(x16) @ W1[e] + b1[e])
// grid (F/128, C/128, E), 256 threads, 2 CTAs/SM
// ---------------------------------------------------------------------------
__global__ __launch_bounds__(256, 2)
void ffn1_mma(const float* __restrict__ b1) {
    extern __shared__ char dynsm[];
    __shared__ int rowTok[128];

    const uint32_t sabs = smem_u32(dynsm);
    const int tid = threadIdx.x, lane = tid & 31, wid = tid >> 5;
    const int wm = wid & 1, wn = wid >> 1;
    const int e = blockIdx.z, m0 = blockIdx.y * 128, n0 = blockIdx.x * 128;

    if (tid < 128) rowTok[tid] = g_slot_token[e * C_CAP + m0 + tid];
    __syncthreads();

    // A loader: row = tid>>1, two 16B chunks at c = (tid&1)*2 + {0,1}
    const int arow = tid >> 1, ac0 = (tid & 1) * 2;
    const int atok = rowTok[arow];
    const uint32_t asz = (atok >= 0) ? 16u : 0u;
    const __half* aSrc = g_x16 + (size_t)(atok < 0 ? 0 : atok) * H_DIM + ac0 * 8;
    const uint32_t aDst = (uint32_t)(arow * 80 + ac0 * 16);

    // B loader: k = tid>>3, 2 chunks at c = (tid&7)*2 + {0,1}, XOR swizzle
    const int bk = tid >> 3, bc0 = (tid & 7) * 2;
    const size_t wBase = (size_t)e * H_DIM * F_DIM + n0;
    const uint32_t bD0 = B_OFF + (uint32_t)(bk * 256) + ((((uint32_t)bc0)      ^ ((uint32_t)bk & 7u)) << 4);
    const uint32_t bD1 = B_OFF + (uint32_t)(bk * 256) + ((((uint32_t)bc0 + 1u) ^ ((uint32_t)bk & 7u)) << 4);

    float acc[4][4][4];
#pragma unroll
    for (int i = 0; i < 4; i++)
#pragma unroll
        for (int j = 0; j < 4; j++)
#pragma unroll
            for (int r = 0; r < 4; r++) acc[i][j][r] = 0.0f;

    const int NCH = H_DIM / 32;   // 32

    auto load_stage = [&](int c) {
        const uint32_t bb = sabs + (uint32_t)((c % STAGES) * BUF_BYTES);
        const int kt = c * 32;
        CP16(bb + aDst,      aSrc + kt,     asz);
        CP16(bb + aDst + 16, aSrc + kt + 8, asz);
        const size_t wrow = wBase + (size_t)(kt + bk) * F_DIM;
        CP16(bb + bD0, g_w1 + wrow + bc0 * 8,     16u);
        CP16(bb + bD1, g_w1 + wrow + bc0 * 8 + 8, 16u);
    };

    load_stage(0); CP_COMMIT();
    load_stage(1); CP_COMMIT();

    for (int c = 0; c < NCH; ++c) {
        CP_WAIT1();
        __syncthreads();
        if (c + 2 < NCH) load_stage(c + 2);
        CP_COMMIT();
        compute_chunk32(sabs + (uint32_t)((c % STAGES) * BUF_BYTES), acc, lane, wm, wn);
    }

    // epilogue: + b1, relu, fp16 store
    const int g = lane >> 2, q = (lane & 3) * 2;
    const float* bp = b1 + (size_t)e * F_DIM + n0;
#pragma unroll
    for (int i = 0; i < 4; ++i) {
        const int r0 = m0 + wm * 64 + i * 16 + g;
        const size_t rowBase0 = ((size_t)e * C_CAP + r0) * F_DIM + n0;
        const size_t rowBase1 = rowBase0 + 8 * F_DIM;
#pragma unroll
        for (int j = 0; j < 4; ++j) {
            const int col = wn * 32 + j * 8 + q;
            const float bc0 = bp[col], bc1 = bp[col + 1];
            float v0 = fmaxf(acc[i][j][0] + bc0, 0.f);
            float v1 = fmaxf(acc[i][j][1] + bc1, 0.f);
            float v2 = fmaxf(acc[i][j][2] + bc0, 0.f);
            float v3 = fmaxf(acc[i][j][3] + bc1, 0.f);
            *reinterpret_cast<uint32_t*>(&g_hidden[rowBase0 + col]) =
                h2_u32(__floats2half2_rn(v0, v1));
            *reinterpret_cast<uint32_t*>(&g_hidden[rowBase1 + col]) =
                h2_u32(__floats2half2_rn(v2, v3));
        }
    }
}

// ---------------------------------------------------------------------------
// FFN2: out[tok] = gate * (hidden @ W2[e] + b2[e]);  K = F_DIM
// grid (H/128, C/128, E), 256 threads, 2 CTAs/SM
// ---------------------------------------------------------------------------
__global__ __launch_bounds__(256, 2)
void ffn2_mma(const float* __restrict__ b2, float* __restrict__ out) {
    extern __shared__ char dynsm[];
    __shared__ int   rowTok[128];
    __shared__ float rowGate[128];

    const uint32_t sabs = smem_u32(dynsm);
    const int tid = threadIdx.x, lane = tid & 31, wid = tid >> 5;
    const int wm = wid & 1, wn = wid >> 1;
    const int e = blockIdx.z, m0 = blockIdx.y * 128, n0 = blockIdx.x * 128;

    if (tid < 128) {
        int tk = g_slot_token[e * C_CAP + m0 + tid];
        rowTok[tid]  = tk;
        rowGate[tid] = (tk >= 0) ? g_gate[tk] : 0.0f;
    }
    __syncthreads();

    const int arow = tid >> 1, ac0 = (tid & 1) * 2;
    const __half* aSrc = g_hidden + ((size_t)e * C_CAP + m0 + arow) * F_DIM + ac0 * 8;
    const uint32_t aDst = (uint32_t)(arow * 80 + ac0 * 16);

    const int bk = tid >> 3, bc0 = (tid & 7) * 2;
    const size_t wBase = (size_t)e * F_DIM * H_DIM + n0;
    const uint32_t bD0 = B_OFF + (uint32_t)(bk * 256) + ((((uint32_t)bc0)      ^ ((uint32_t)bk & 7u)) << 4);
    const uint32_t bD1 = B_OFF + (uint32_t)(bk * 256) + ((((uint32_t)bc0 + 1u) ^ ((uint32_t)bk & 7u)) << 4);

    float acc[4][4][4];
#pragma unroll
    for (int i = 0; i < 4; i++)
#pragma unroll
        for (int j = 0; j < 4; j++)
#pragma unroll
            for (int r = 0; r < 4; r++) acc[i][j][r] = 0.0f;

    const int NCH = F_DIM / 32;   // 128

    auto load_stage = [&](int c) {
        const uint32_t bb = sabs + (uint32_t)((c % STAGES) * BUF_BYTES);
        const int kt = c * 32;
        CP16(bb + aDst,      aSrc + kt,     16u);
        CP16(bb + aDst + 16, aSrc + kt + 8, 16u);
        const size_t wrow = wBase + (size_t)(kt + bk) * H_DIM;
        CP16(bb + bD0, g_w2 + wrow + bc0 * 8,     16u);
        CP16(bb + bD1, g_w2 + wrow + bc0 * 8 + 8, 16u);
    };

    load_stage(0); CP_COMMIT();
    load_stage(1); CP_COMMIT();

    for (int c = 0; c < NCH; ++c) {
        CP_WAIT1();
        __syncthreads();
        if (c + 2 < NCH) load_stage(c + 2);
        CP_COMMIT();
        compute_chunk32(sabs + (uint32_t)((c % STAGES) * BUF_BYTES), acc, lane, wm, wn);
    }

    // epilogue: + b2, gate, scatter fp32
    const int g = lane >> 2, q = (lane & 3) * 2;
    const float* bp = b2 + (size_t)e * H_DIM + n0;
#pragma unroll
    for (int i = 0; i < 4; ++i) {
        const int rl0 = wm * 64 + i * 16 + g;
        const int rl1 = rl0 + 8;
        const int tok0 = rowTok[rl0], tok1 = rowTok[rl1];
        const float g0 = rowGate[rl0], g1 = rowGate[rl1];
#pragma unroll
        for (int j = 0; j < 4; ++j) {
            const int col = wn * 32 + j * 8 + q;
            const float bc0 = bp[col], bc1 = bp[col + 1];
            if (tok0 >= 0) {
                float2 o;
                o.x = g0 * (acc[i][j][0] + bc0);
                o.y = g0 * (acc[i][j][1] + bc1);
                *reinterpret_cast<float2*>(out + (size_t)tok0 * H_DIM + n0 + col) = o;
            }
            if (tok1 >= 0) {
                float2 o;
                o.x = g1 * (acc[i][j][2] + bc0);
                o.y = g1 * (acc[i][j][3] + bc1);
                *reinterpret_cast<float2*>(out + (size_t)tok1 * H_DIM + n0 + col) = o;
            }
        }
    }
}

// ---------------------------------------------------------------------------
// Launcher
// ---------------------------------------------------------------------------
extern "C" void kernel_launch(void* const* d_in, const int* in_sizes, int n_in,
                              void* d_out, int out_size) {
    const float* x  = (const float*)d_in[0];
    const float* Wg = (const float*)d_in[1];
    const float* W1 = (const float*)d_in[2];
    const float* b1 = (const float*)d_in[3];
    const float* W2 = (const float*)d_in[4];
    const float* b2 = (const float*)d_in[5];
    float* out = (float*)d_out;

    cudaFuncSetAttribute(ffn1_mma, cudaFuncAttributeMaxDynamicSharedMemorySize, DYN_SMEM);
    cudaFuncSetAttribute(ffn2_mma, cudaFuncAttributeMaxDynamicSharedMemorySize, DYN_SMEM);

    cudaMemsetAsync(out, 0, (size_t)out_size * sizeof(float));

    __half *xp, *w1p, *w2p;
    cudaGetSymbolAddress((void**)&xp,  g_x16);
    cudaGetSymbolAddress((void**)&w1p, g_w1);
    cudaGetSymbolAddress((void**)&w2p, g_w2);

    const int nx = T_TOK * H_DIM / 8;
    const int nw = E_NUM * H_DIM * F_DIM / 8;
    convh_kernel<<<(nx + 255) / 256, 256>>>(x,  xp,  nx);
    convh_kernel<<<(nw + 255) / 256, 256>>>(W1, w1p, nw);
    convh_kernel<<<(nw + 255) / 256, 256>>>(W2, w2p, nw);

    gating_kernel<<<T_TOK / 8, 256>>>(x, Wg);
    assign_kernel<<<1, 256>>>();

    dim3 g1(F_DIM / 128, C_CAP / 128, E_NUM);   // (32, 8, 8)
    ffn1_mma<<<g1, 256, DYN_SMEM>>>(b1);

    dim3 g2(H_DIM / 128, C_CAP / 128, E_NUM);   // (8, 8, 8)
    ffn2_mma<<<g2, 256, DYN_SMEM>>>(b2, out);
}